// round 2
// baseline (speedup 1.0000x reference)
#include <cuda_runtime.h>
#include <cuda_bf16.h>
#include <math.h>

// ---------------- problem constants ----------------
#define NNODES 100000
#define NEDGES 400000
#define ETOT   (NEDGES + NNODES)   // with self loops = 500000
#define NGRAPH 4000
#define F_IN   32
#define HID    128
#define NHEAD  3
#define W3     (NHEAD * HID)       // 384
#define NCLS   10
#define NLAY   4
#define NEG_SLOPE 0.2f

#define CDIV(a,b) (((a)+(b)-1)/(b))

// ---------------- scratch (device globals, no allocation) ----------------
__device__ float    g_bufA[(size_t)NNODES * W3];   // GEMM output / Hw
__device__ float    g_bufB[(size_t)NNODES * W3];   // layer in/out (stem intermediate reuses g_bufA)
__device__ float    g_es[NNODES * NHEAD];
__device__ float    g_ed[NNODES * NHEAD];
__device__ float    g_edge[(size_t)ETOT * NHEAD];  // e then p, in place
__device__ unsigned g_max[NNODES * NHEAD];         // ordered-int encoded segment max
__device__ float    g_sum[NNODES * NHEAD];
__device__ float    g_colsum[W3];
__device__ float    g_colsq[W3];
__device__ float    g_pool[(size_t)NGRAPH * W3];
__device__ float    g_cnt[NGRAPH];

// ---------------- float ordered-int encoding for atomicMax ----------------
__device__ __forceinline__ unsigned encf(float f) {
    unsigned u = __float_as_uint(f);
    return (u & 0x80000000u) ? ~u : (u | 0x80000000u);
}
__device__ __forceinline__ float decf(unsigned u) {
    return __uint_as_float((u & 0x80000000u) ? (u & 0x7fffffffu) : ~u);
}
#define ENC_NEG_INF 0x007FFFFFu   // encf(-inf)

// ---------------- tiled SGEMM: C[M,Nw] = A[M,K] @ B[K,Nw] (+bias, relu) ----
#define BM 64
#define BN 64
#define BK 16
__global__ void gemm_kernel(const float* __restrict__ A, const float* __restrict__ B,
                            const float* __restrict__ bias, float* __restrict__ C,
                            int M, int Nw, int K, int relu)
{
    __shared__ float As[BK][BM];
    __shared__ float Bs[BK][BN];

    const int bm = blockIdx.y * BM;
    const int bn = blockIdx.x * BN;
    const int tid = threadIdx.x;           // 256 threads
    const int tx = tid & 15;
    const int ty = tid >> 4;

    const int arow  = tid >> 2;            // 0..63
    const int acol4 = (tid & 3) << 2;      // 0,4,8,12
    const int brow  = tid >> 4;            // 0..15
    const int bcol4 = (tid & 15) << 2;     // 0..60

    float acc[4][4];
#pragma unroll
    for (int i = 0; i < 4; i++)
#pragma unroll
        for (int j = 0; j < 4; j++) acc[i][j] = 0.f;

    for (int k0 = 0; k0 < K; k0 += BK) {
        // load A tile (transposed into smem)
        float4 av = make_float4(0.f, 0.f, 0.f, 0.f);
        int gr = bm + arow;
        if (gr < M)
            av = *reinterpret_cast<const float4*>(A + (size_t)gr * K + k0 + acol4);
        As[acol4 + 0][arow] = av.x;
        As[acol4 + 1][arow] = av.y;
        As[acol4 + 2][arow] = av.z;
        As[acol4 + 3][arow] = av.w;
        // load B tile
        float4 bv = *reinterpret_cast<const float4*>(B + (size_t)(k0 + brow) * Nw + bn + bcol4);
        *reinterpret_cast<float4*>(&Bs[brow][bcol4]) = bv;
        __syncthreads();

#pragma unroll
        for (int k = 0; k < BK; k++) {
            float a0 = As[k][ty * 4 + 0];
            float a1 = As[k][ty * 4 + 1];
            float a2 = As[k][ty * 4 + 2];
            float a3 = As[k][ty * 4 + 3];
            float4 bq = *reinterpret_cast<const float4*>(&Bs[k][tx * 4]);
            acc[0][0] += a0 * bq.x; acc[0][1] += a0 * bq.y; acc[0][2] += a0 * bq.z; acc[0][3] += a0 * bq.w;
            acc[1][0] += a1 * bq.x; acc[1][1] += a1 * bq.y; acc[1][2] += a1 * bq.z; acc[1][3] += a1 * bq.w;
            acc[2][0] += a2 * bq.x; acc[2][1] += a2 * bq.y; acc[2][2] += a2 * bq.z; acc[2][3] += a2 * bq.w;
            acc[3][0] += a3 * bq.x; acc[3][1] += a3 * bq.y; acc[3][2] += a3 * bq.z; acc[3][3] += a3 * bq.w;
        }
        __syncthreads();
    }

#pragma unroll
    for (int i = 0; i < 4; i++) {
        int row = bm + ty * 4 + i;
        if (row >= M) continue;
#pragma unroll
        for (int j = 0; j < 4; j++) {
            int col = bn + tx * 4 + j;
            float v = acc[i][j];
            if (bias) v += bias[col];
            if (relu) v = fmaxf(v, 0.f);
            C[(size_t)row * Nw + col] = v;
        }
    }
}

// ---------------- attention coefficients: es/ed per (node, head) ----------
__global__ void attn_coef_kernel(const float* __restrict__ asrc, const float* __restrict__ adst)
{
    int gw = (blockIdx.x * blockDim.x + threadIdx.x) >> 5;
    int lane = threadIdx.x & 31;
    if (gw >= NNODES * NHEAD) return;
    int n = gw / NHEAD, h = gw % NHEAD;
    float4 v = reinterpret_cast<const float4*>(g_bufA + (size_t)n * W3 + h * HID)[lane];
    float4 a = reinterpret_cast<const float4*>(asrc + h * HID)[lane];
    float4 b = reinterpret_cast<const float4*>(adst + h * HID)[lane];
    float s = v.x * a.x + v.y * a.y + v.z * a.z + v.w * a.w;
    float d = v.x * b.x + v.y * b.y + v.z * b.z + v.w * b.w;
#pragma unroll
    for (int o = 16; o > 0; o >>= 1) {
        s += __shfl_down_sync(0xffffffffu, s, o);
        d += __shfl_down_sync(0xffffffffu, d, o);
    }
    if (lane == 0) { g_es[gw] = s; g_ed[gw] = d; }
}

// ---------------- per-layer init: segment max/sum -------------------------
__global__ void init_ms_kernel()
{
    int i = blockIdx.x * blockDim.x + threadIdx.x;
    if (i < NNODES * NHEAD) { g_max[i] = ENC_NEG_INF; g_sum[i] = 0.f; }
}

// ---------------- edge scores + segment max -------------------------------
__global__ void edge_score_kernel(const int* __restrict__ ei)
{
    int i = blockIdx.x * blockDim.x + threadIdx.x;
    if (i >= ETOT) return;
    int s = (i < NEDGES) ? ei[i] : (i - NEDGES);
    int d = (i < NEDGES) ? ei[NEDGES + i] : (i - NEDGES);
#pragma unroll
    for (int h = 0; h < NHEAD; h++) {
        float e = g_es[s * NHEAD + h] + g_ed[d * NHEAD + h];
        e = (e > 0.f) ? e : NEG_SLOPE * e;
        g_edge[(size_t)i * NHEAD + h] = e;
        atomicMax(&g_max[d * NHEAD + h], encf(e));
    }
}

// ---------------- p = exp(e - max), segment sum ----------------------------
__global__ void edge_p_kernel(const int* __restrict__ ei)
{
    int i = blockIdx.x * blockDim.x + threadIdx.x;
    if (i >= ETOT) return;
    int d = (i < NEDGES) ? ei[NEDGES + i] : (i - NEDGES);
#pragma unroll
    for (int h = 0; h < NHEAD; h++) {
        float p = expf(g_edge[(size_t)i * NHEAD + h] - decf(g_max[d * NHEAD + h]));
        g_edge[(size_t)i * NHEAD + h] = p;
        atomicAdd(&g_sum[d * NHEAD + h], p);
    }
}

// ---------------- init output buffer to bias -------------------------------
__global__ void init_out_kernel(const float* __restrict__ bias)
{
    int idx = blockIdx.x * blockDim.x + threadIdx.x;
    int total = NNODES * W3;
    for (; idx < total; idx += gridDim.x * blockDim.x)
        g_bufB[idx] = bias[idx % W3];
}

// ---------------- aggregation: out[dst] += alpha * Hw[src] -----------------
__global__ void aggregate_kernel(const int* __restrict__ ei)
{
    int gw = (blockIdx.x * blockDim.x + threadIdx.x) >> 5;
    int lane = threadIdx.x & 31;
    if (gw >= ETOT * NHEAD) return;
    int i = gw / NHEAD, h = gw % NHEAD;
    int s = (i < NEDGES) ? ei[i] : (i - NEDGES);
    int d = (i < NEDGES) ? ei[NEDGES + i] : (i - NEDGES);
    float alpha = g_edge[(size_t)i * NHEAD + h] / g_sum[d * NHEAD + h];
    float4 v = reinterpret_cast<const float4*>(g_bufA + (size_t)s * W3 + h * HID)[lane];
    float* o = g_bufB + (size_t)d * W3 + h * HID + lane * 4;
    atomicAdd(o + 0, alpha * v.x);
    atomicAdd(o + 1, alpha * v.y);
    atomicAdd(o + 2, alpha * v.z);
    atomicAdd(o + 3, alpha * v.w);
}

// ---------------- batchnorm -----------------------------------------------
__global__ void bn_zero_kernel()
{
    int i = blockIdx.x * blockDim.x + threadIdx.x;
    if (i < W3) { g_colsum[i] = 0.f; g_colsq[i] = 0.f; }
}

__global__ void bn_reduce_kernel()
{
    int warp = (blockIdx.x * blockDim.x + threadIdx.x) >> 5;
    int lane = threadIdx.x & 31;
    int nwarps = (gridDim.x * blockDim.x) >> 5;
    float s[12], q[12];
#pragma unroll
    for (int j = 0; j < 12; j++) { s[j] = 0.f; q[j] = 0.f; }
    for (int r = warp; r < NNODES; r += nwarps) {
        const float* row = g_bufB + (size_t)r * W3;
#pragma unroll
        for (int j = 0; j < 12; j++) {
            float v = row[lane + j * 32];
            s[j] += v; q[j] += v * v;
        }
    }
#pragma unroll
    for (int j = 0; j < 12; j++) {
        atomicAdd(&g_colsum[lane + j * 32], s[j]);
        atomicAdd(&g_colsq[lane + j * 32], q[j]);
    }
}

__global__ void bn_norm_kernel(const float* __restrict__ gam, const float* __restrict__ bet)
{
    int idx = blockIdx.x * blockDim.x + threadIdx.x;
    int total = NNODES * W3;
    const float invN = 1.f / (float)NNODES;
    for (; idx < total; idx += gridDim.x * blockDim.x) {
        int j = idx % W3;
        float mu = g_colsum[j] * invN;
        float var = g_colsq[j] * invN - mu * mu;
        g_bufB[idx] = (g_bufB[idx] - mu) * rsqrtf(var + 1e-5f) * gam[j] + bet[j];
    }
}

// ---------------- mean pool -------------------------------------------------
__global__ void pool_zero_kernel()
{
    int idx = blockIdx.x * blockDim.x + threadIdx.x;
    int total = NGRAPH * W3;
    for (; idx < total; idx += gridDim.x * blockDim.x) g_pool[idx] = 0.f;
    if (blockIdx.x == 0 && threadIdx.x < NGRAPH) { }  // cnt handled below
    for (int i = blockIdx.x * blockDim.x + threadIdx.x; i < NGRAPH; i += gridDim.x * blockDim.x)
        g_cnt[i] = 0.f;
}

__global__ void pool_kernel(const int* __restrict__ batch)
{
    int gw = (blockIdx.x * blockDim.x + threadIdx.x) >> 5;
    int lane = threadIdx.x & 31;
    if (gw >= NNODES) return;
    int g = batch[gw];
    const float* row = g_bufB + (size_t)gw * W3;
#pragma unroll
    for (int j = 0; j < 12; j++)
        atomicAdd(&g_pool[(size_t)g * W3 + lane + j * 32], row[lane + j * 32]);
    if (lane == 0) atomicAdd(&g_cnt[g], 1.f);
}

// ---------------- head: mean, lin3+relu, lin4, log_softmax -----------------
__global__ void head_kernel(const float* __restrict__ w3, const float* __restrict__ b3,
                            const float* __restrict__ w4, const float* __restrict__ b4,
                            float* __restrict__ out)
{
    __shared__ float gv[W3];
    __shared__ float hid[HID];
    __shared__ float lg[NCLS];
    int g = blockIdx.x;
    int t = threadIdx.x;   // 128 threads
    float c = fmaxf(g_cnt[g], 1.f);
    for (int j = t; j < W3; j += 128) gv[j] = g_pool[(size_t)g * W3 + j] / c;
    __syncthreads();
    float acc = b3[t];
    for (int k = 0; k < W3; k++) acc += gv[k] * w3[k * HID + t];
    hid[t] = fmaxf(acc, 0.f);
    __syncthreads();
    if (t < NCLS) {
        float a = b4[t];
        for (int k = 0; k < HID; k++) a += hid[k] * w4[k * NCLS + t];
        lg[t] = a;
    }
    __syncthreads();
    if (t == 0) {
        float mx = lg[0];
        for (int c2 = 1; c2 < NCLS; c2++) mx = fmaxf(mx, lg[c2]);
        float se = 0.f;
        for (int c2 = 0; c2 < NCLS; c2++) se += expf(lg[c2] - mx);
        float l = mx + logf(se);
        for (int c2 = 0; c2 < NCLS; c2++) out[g * NCLS + c2] = lg[c2] - l;
    }
}

// ---------------- host orchestration ---------------------------------------
static void run_gat_layer(const float* in_ptr, int fin,
                          const float* W, const float* a_s, const float* a_d,
                          const float* bias, const float* gam, const float* bet,
                          const int* ei, float* bufA, float* bufB)
{
    // Hw = in @ W   (no bias, no relu)
    {
        dim3 grid(W3 / BN, CDIV(NNODES, BM));
        gemm_kernel<<<grid, 256>>>(in_ptr, W, nullptr, bufA, NNODES, W3, fin, 0);
    }
    // attention coefficients
    attn_coef_kernel<<<CDIV(NNODES * NHEAD * 32, 256), 256>>>(a_s, a_d);
    // segment max/sum init
    init_ms_kernel<<<CDIV(NNODES * NHEAD, 256), 256>>>();
    // edge scores + max
    edge_score_kernel<<<CDIV(ETOT, 256), 256>>>(ei);
    // exp + sum
    edge_p_kernel<<<CDIV(ETOT, 256), 256>>>(ei);
    // out = bias
    init_out_kernel<<<2048, 256>>>(bias);
    // aggregate
    aggregate_kernel<<<CDIV((size_t)ETOT * NHEAD * 32, 256), 256>>>(ei);
    // batchnorm
    bn_zero_kernel<<<2, 256>>>();
    bn_reduce_kernel<<<512, 256>>>();
    bn_norm_kernel<<<2048, 256>>>(gam, bet);
}

extern "C" void kernel_launch(void* const* d_in, const int* in_sizes, int n_in,
                              void* d_out, int out_size)
{
    const float* x       = (const float*)d_in[0];
    const int*   ei      = (const int*)  d_in[1];
    const int*   batch   = (const int*)  d_in[2];
    const float* lin1_w  = (const float*)d_in[3];
    const float* lin1_b  = (const float*)d_in[4];
    const float* lin2_w  = (const float*)d_in[5];
    const float* lin2_b  = (const float*)d_in[6];
    const float* w0      = (const float*)d_in[7];
    const float* as0     = (const float*)d_in[8];
    const float* ad0     = (const float*)d_in[9];
    const float* b0      = (const float*)d_in[10];
    const float* wl      = (const float*)d_in[11];
    const float* asl     = (const float*)d_in[12];
    const float* adl     = (const float*)d_in[13];
    const float* bl      = (const float*)d_in[14];
    const float* gamma   = (const float*)d_in[15];
    const float* beta    = (const float*)d_in[16];
    const float* lin3_w  = (const float*)d_in[17];
    const float* lin3_b  = (const float*)d_in[18];
    const float* lin4_w  = (const float*)d_in[19];
    const float* lin4_b  = (const float*)d_in[20];
    float* out = (float*)d_out;

    float *bufA, *bufB;
    cudaGetSymbolAddress((void**)&bufA, g_bufA);
    cudaGetSymbolAddress((void**)&bufB, g_bufB);

    // ---- MLP stem ----
    {
        dim3 grid1(256 / BN, CDIV(NNODES, BM));
        gemm_kernel<<<grid1, 256>>>(x, lin1_w, lin1_b, bufA, NNODES, 2 * HID, F_IN, 1);
        dim3 grid2(HID / BN, CDIV(NNODES, BM));
        gemm_kernel<<<grid2, 256>>>(bufA, lin2_w, lin2_b, bufB, NNODES, HID, 2 * HID, 1);
    }

    // ---- GAT layer 0 (HID -> W3) ----
    run_gat_layer(bufB, HID, w0, as0, ad0, b0, gamma + 0 * W3, beta + 0 * W3, ei, bufA, bufB);

    // ---- GAT layers 1..3 (W3 -> W3) ----
    for (int i = 0; i < NLAY - 1; i++) {
        run_gat_layer(bufB, W3,
                      wl + (size_t)i * W3 * W3,
                      asl + (size_t)i * NHEAD * HID,
                      adl + (size_t)i * NHEAD * HID,
                      bl + (size_t)i * W3,
                      gamma + (size_t)(i + 1) * W3,
                      beta + (size_t)(i + 1) * W3,
                      ei, bufA, bufB);
    }

    // ---- global mean pool + head ----
    pool_zero_kernel<<<1024, 256>>>();
    pool_kernel<<<CDIV(NNODES * 32, 256), 256>>>(batch);
    head_kernel<<<NGRAPH, 128>>>(lin3_w, lin3_b, lin4_w, lin4_b, out);
}

// round 5
// speedup vs baseline: 1.3570x; 1.3570x over previous
#include <cuda_runtime.h>
#include <cuda_bf16.h>
#include <math.h>

// ---------------- problem constants ----------------
#define NNODES 100000
#define NEDGES 400000
#define ETOT   (NEDGES + NNODES)   // with self loops = 500000
#define NGRAPH 4000
#define F_IN   32
#define HID    128
#define NHEAD  3
#define W3     (NHEAD * HID)       // 384
#define NCLS   10
#define NLAY   4
#define NEG_SLOPE 0.2f

#define CDIV(a,b) (((a)+(b)-1)/(b))

#define SCAN_B 256
#define NBLK_SCAN CDIV(NNODES, SCAN_B)   // 391

// ---------------- scratch (device globals, no allocation) ----------------
__device__ float g_bufA[(size_t)NNODES * W3];   // GEMM output / Hw
__device__ float g_bufB[(size_t)NNODES * W3];   // layer in/out
__device__ float g_es[NNODES * NHEAD];
__device__ float g_ed[NNODES * NHEAD];
__device__ int   g_deg[NNODES];
__device__ int   g_off[NNODES + 1];
__device__ int   g_bsum[512];
__device__ int   g_cur[NNODES];
__device__ int   g_csr_src[ETOT];
__device__ float g_colsum[W3];
__device__ float g_colsq[W3];
__device__ float g_pool[(size_t)NGRAPH * W3];
__device__ float g_cnt[NGRAPH];

// ---------------- tiled SGEMM: C[M,Nw] = A[M,K] @ B[K,Nw] (+bias, relu) ----
#define BM 64
#define BN 64
#define BK 16
__global__ void gemm_kernel(const float* __restrict__ A, const float* __restrict__ B,
                            const float* __restrict__ bias, float* __restrict__ C,
                            int M, int Nw, int K, int relu)
{
    __shared__ float As[BK][BM];
    __shared__ float Bs[BK][BN];

    const int bm = blockIdx.y * BM;
    const int bn = blockIdx.x * BN;
    const int tid = threadIdx.x;           // 256 threads
    const int tx = tid & 15;
    const int ty = tid >> 4;

    const int arow  = tid >> 2;            // 0..63
    const int acol4 = (tid & 3) << 2;      // 0,4,8,12
    const int brow  = tid >> 4;            // 0..15
    const int bcol4 = (tid & 15) << 2;     // 0..60

    float acc[4][4];
#pragma unroll
    for (int i = 0; i < 4; i++)
#pragma unroll
        for (int j = 0; j < 4; j++) acc[i][j] = 0.f;

    for (int k0 = 0; k0 < K; k0 += BK) {
        float4 av = make_float4(0.f, 0.f, 0.f, 0.f);
        int gr = bm + arow;
        if (gr < M)
            av = *reinterpret_cast<const float4*>(A + (size_t)gr * K + k0 + acol4);
        As[acol4 + 0][arow] = av.x;
        As[acol4 + 1][arow] = av.y;
        As[acol4 + 2][arow] = av.z;
        As[acol4 + 3][arow] = av.w;
        float4 bv = *reinterpret_cast<const float4*>(B + (size_t)(k0 + brow) * Nw + bn + bcol4);
        *reinterpret_cast<float4*>(&Bs[brow][bcol4]) = bv;
        __syncthreads();

#pragma unroll
        for (int k = 0; k < BK; k++) {
            float a0 = As[k][ty * 4 + 0];
            float a1 = As[k][ty * 4 + 1];
            float a2 = As[k][ty * 4 + 2];
            float a3 = As[k][ty * 4 + 3];
            float4 bq = *reinterpret_cast<const float4*>(&Bs[k][tx * 4]);
            acc[0][0] += a0 * bq.x; acc[0][1] += a0 * bq.y; acc[0][2] += a0 * bq.z; acc[0][3] += a0 * bq.w;
            acc[1][0] += a1 * bq.x; acc[1][1] += a1 * bq.y; acc[1][2] += a1 * bq.z; acc[1][3] += a1 * bq.w;
            acc[2][0] += a2 * bq.x; acc[2][1] += a2 * bq.y; acc[2][2] += a2 * bq.z; acc[2][3] += a2 * bq.w;
            acc[3][0] += a3 * bq.x; acc[3][1] += a3 * bq.y; acc[3][2] += a3 * bq.z; acc[3][3] += a3 * bq.w;
        }
        __syncthreads();
    }

#pragma unroll
    for (int i = 0; i < 4; i++) {
        int row = bm + ty * 4 + i;
        if (row >= M) continue;
#pragma unroll
        for (int j = 0; j < 4; j++) {
            int col = bn + tx * 4 + j;
            float v = acc[i][j];
            if (bias) v += bias[col];
            if (relu) v = fmaxf(v, 0.f);
            C[(size_t)row * Nw + col] = v;
        }
    }
}

// ---------------- CSR build ------------------------------------------------
__global__ void csr_zero_kernel()
{
    int i = blockIdx.x * blockDim.x + threadIdx.x;
    if (i < NNODES) { g_deg[i] = 0; g_cur[i] = 0; }
}

__global__ void csr_count_kernel(const int* __restrict__ ei)
{
    int i = blockIdx.x * blockDim.x + threadIdx.x;
    if (i >= ETOT) return;
    int d = (i < NEDGES) ? ei[NEDGES + i] : (i - NEDGES);
    atomicAdd(&g_deg[d], 1);
}

__global__ void scan1_kernel()
{
    __shared__ int sh[SCAN_B];
    int t = threadIdx.x;
    int i = blockIdx.x * SCAN_B + t;
    int v = (i < NNODES) ? g_deg[i] : 0;
    sh[t] = v;
    __syncthreads();
#pragma unroll
    for (int o = 1; o < SCAN_B; o <<= 1) {
        int x = (t >= o) ? sh[t - o] : 0;
        __syncthreads();
        sh[t] += x;
        __syncthreads();
    }
    if (i < NNODES) g_off[i] = sh[t] - v;           // exclusive within block
    if (t == SCAN_B - 1) g_bsum[blockIdx.x] = sh[t];
}

__global__ void scan2_kernel()
{
    __shared__ int sh[512];
    int t = threadIdx.x;  // 512 threads
    int v = (t < NBLK_SCAN) ? g_bsum[t] : 0;
    sh[t] = v;
    __syncthreads();
#pragma unroll
    for (int o = 1; o < 512; o <<= 1) {
        int x = (t >= o) ? sh[t - o] : 0;
        __syncthreads();
        sh[t] += x;
        __syncthreads();
    }
    if (t < NBLK_SCAN) g_bsum[t] = sh[t] - v;       // exclusive block offsets
}

__global__ void scan3_kernel()
{
    int i = blockIdx.x * blockDim.x + threadIdx.x;
    if (i < NNODES) g_off[i] += g_bsum[i / SCAN_B];
    if (i == 0) g_off[NNODES] = ETOT;
}

__global__ void csr_scatter_kernel(const int* __restrict__ ei)
{
    int i = blockIdx.x * blockDim.x + threadIdx.x;
    if (i >= ETOT) return;
    int s = (i < NEDGES) ? ei[i] : (i - NEDGES);
    int d = (i < NEDGES) ? ei[NEDGES + i] : (i - NEDGES);
    int pos = g_off[d] + atomicAdd(&g_cur[d], 1);
    g_csr_src[pos] = s;
}

// ---------------- attention coefficients: es/ed per (node, head) ----------
__global__ void attn_coef_kernel(const float* __restrict__ asrc, const float* __restrict__ adst)
{
    int gw = (blockIdx.x * blockDim.x + threadIdx.x) >> 5;
    int lane = threadIdx.x & 31;
    if (gw >= NNODES * NHEAD) return;
    int n = gw / NHEAD, h = gw % NHEAD;
    float4 v = reinterpret_cast<const float4*>(g_bufA + (size_t)n * W3 + h * HID)[lane];
    float4 a = reinterpret_cast<const float4*>(asrc + h * HID)[lane];
    float4 b = reinterpret_cast<const float4*>(adst + h * HID)[lane];
    float s = v.x * a.x + v.y * a.y + v.z * a.z + v.w * a.w;
    float d = v.x * b.x + v.y * b.y + v.z * b.z + v.w * b.w;
#pragma unroll
    for (int o = 16; o > 0; o >>= 1) {
        s += __shfl_down_sync(0xffffffffu, s, o);
        d += __shfl_down_sync(0xffffffffu, d, o);
    }
    if (lane == 0) { g_es[gw] = s; g_ed[gw] = d; }
}

// ---------------- fused segment-softmax + aggregation (warp per node) ------
__device__ __forceinline__ float lrelu(float x) {
    return (x > 0.f) ? x : NEG_SLOPE * x;
}

__global__ void gat_agg_kernel(const float* __restrict__ bias)
{
    int gw = (blockIdx.x * blockDim.x + threadIdx.x) >> 5;
    int lane = threadIdx.x & 31;
    if (gw >= NNODES) return;
    const int n = gw;
    const int off0 = g_off[n];
    const int off1 = g_off[n + 1];

    const float ed0 = g_ed[n * 3 + 0];
    const float ed1 = g_ed[n * 3 + 1];
    const float ed2 = g_ed[n * 3 + 2];

    // pass A1: per-head max over incoming edges (lanes split edges)
    float m0 = -1e30f, m1 = -1e30f, m2 = -1e30f;
    for (int e = off0 + lane; e < off1; e += 32) {
        int s = g_csr_src[e];
        m0 = fmaxf(m0, lrelu(g_es[s * 3 + 0] + ed0));
        m1 = fmaxf(m1, lrelu(g_es[s * 3 + 1] + ed1));
        m2 = fmaxf(m2, lrelu(g_es[s * 3 + 2] + ed2));
    }
#pragma unroll
    for (int o = 16; o > 0; o >>= 1) {
        m0 = fmaxf(m0, __shfl_xor_sync(0xffffffffu, m0, o));
        m1 = fmaxf(m1, __shfl_xor_sync(0xffffffffu, m1, o));
        m2 = fmaxf(m2, __shfl_xor_sync(0xffffffffu, m2, o));
    }
    // pass A2: sum of exp
    float s0 = 0.f, s1 = 0.f, s2 = 0.f;
    for (int e = off0 + lane; e < off1; e += 32) {
        int s = g_csr_src[e];
        s0 += __expf(lrelu(g_es[s * 3 + 0] + ed0) - m0);
        s1 += __expf(lrelu(g_es[s * 3 + 1] + ed1) - m1);
        s2 += __expf(lrelu(g_es[s * 3 + 2] + ed2) - m2);
    }
#pragma unroll
    for (int o = 16; o > 0; o >>= 1) {
        s0 += __shfl_xor_sync(0xffffffffu, s0, o);
        s1 += __shfl_xor_sync(0xffffffffu, s1, o);
        s2 += __shfl_xor_sync(0xffffffffu, s2, o);
    }
    const float r0 = 1.f / s0, r1 = 1.f / s1, r2 = 1.f / s2;

    // pass B: gather + weighted accumulate, lanes split the 384 features
    float acc[12];
#pragma unroll
    for (int j = 0; j < 12; j++) acc[j] = 0.f;

    for (int e = off0; e < off1; e++) {
        int s = g_csr_src[e];                       // broadcast load
        float a0 = __expf(lrelu(g_es[s * 3 + 0] + ed0) - m0) * r0;
        float a1 = __expf(lrelu(g_es[s * 3 + 1] + ed1) - m1) * r1;
        float a2 = __expf(lrelu(g_es[s * 3 + 2] + ed2) - m2) * r2;
        const float* hp = g_bufA + (size_t)s * W3;
#pragma unroll
        for (int j = 0; j < 12; j++) {
            float al = (j < 4) ? a0 : ((j < 8) ? a1 : a2);
            acc[j] = fmaf(al, hp[j * 32 + lane], acc[j]);
        }
    }
    float* op = g_bufB + (size_t)n * W3;
#pragma unroll
    for (int j = 0; j < 12; j++)
        op[j * 32 + lane] = acc[j] + bias[j * 32 + lane];
}

// ---------------- batchnorm -----------------------------------------------
__global__ void bn_zero_kernel()
{
    int i = blockIdx.x * blockDim.x + threadIdx.x;
    if (i < W3) { g_colsum[i] = 0.f; g_colsq[i] = 0.f; }
}

__global__ void bn_reduce_kernel()
{
    int warp = (blockIdx.x * blockDim.x + threadIdx.x) >> 5;
    int lane = threadIdx.x & 31;
    int nwarps = (gridDim.x * blockDim.x) >> 5;
    float s[12], q[12];
#pragma unroll
    for (int j = 0; j < 12; j++) { s[j] = 0.f; q[j] = 0.f; }
    for (int r = warp; r < NNODES; r += nwarps) {
        const float* row = g_bufB + (size_t)r * W3;
#pragma unroll
        for (int j = 0; j < 12; j++) {
            float v = row[lane + j * 32];
            s[j] += v; q[j] += v * v;
        }
    }
#pragma unroll
    for (int j = 0; j < 12; j++) {
        atomicAdd(&g_colsum[lane + j * 32], s[j]);
        atomicAdd(&g_colsq[lane + j * 32], q[j]);
    }
}

__global__ void bn_norm_kernel(const float* __restrict__ gam, const float* __restrict__ bet)
{
    int idx = blockIdx.x * blockDim.x + threadIdx.x;
    int total = NNODES * W3;
    const float invN = 1.f / (float)NNODES;
    for (; idx < total; idx += gridDim.x * blockDim.x) {
        int j = idx % W3;
        float mu = g_colsum[j] * invN;
        float var = g_colsq[j] * invN - mu * mu;
        g_bufB[idx] = (g_bufB[idx] - mu) * rsqrtf(var + 1e-5f) * gam[j] + bet[j];
    }
}

// ---------------- mean pool -------------------------------------------------
__global__ void pool_zero_kernel()
{
    int idx = blockIdx.x * blockDim.x + threadIdx.x;
    int total = NGRAPH * W3;
    for (; idx < total; idx += gridDim.x * blockDim.x) g_pool[idx] = 0.f;
    for (int i = blockIdx.x * blockDim.x + threadIdx.x; i < NGRAPH; i += gridDim.x * blockDim.x)
        g_cnt[i] = 0.f;
}

__global__ void pool_kernel(const int* __restrict__ batch)
{
    int gw = (blockIdx.x * blockDim.x + threadIdx.x) >> 5;
    int lane = threadIdx.x & 31;
    if (gw >= NNODES) return;
    int g = batch[gw];
    const float* row = g_bufB + (size_t)gw * W3;
#pragma unroll
    for (int j = 0; j < 12; j++)
        atomicAdd(&g_pool[(size_t)g * W3 + lane + j * 32], row[lane + j * 32]);
    if (lane == 0) atomicAdd(&g_cnt[g], 1.f);
}

// ---------------- head: mean, lin3+relu, lin4, log_softmax -----------------
__global__ void head_kernel(const float* __restrict__ w3, const float* __restrict__ b3,
                            const float* __restrict__ w4, const float* __restrict__ b4,
                            float* __restrict__ out)
{
    __shared__ float gv[W3];
    __shared__ float hid[HID];
    __shared__ float lg[NCLS];
    int g = blockIdx.x;
    int t = threadIdx.x;   // 128 threads
    float c = fmaxf(g_cnt[g], 1.f);
    for (int j = t; j < W3; j += 128) gv[j] = g_pool[(size_t)g * W3 + j] / c;
    __syncthreads();
    float acc = b3[t];
    for (int k = 0; k < W3; k++) acc += gv[k] * w3[k * HID + t];
    hid[t] = fmaxf(acc, 0.f);
    __syncthreads();
    if (t < NCLS) {
        float a = b4[t];
        for (int k = 0; k < HID; k++) a += hid[k] * w4[k * NCLS + t];
        lg[t] = a;
    }
    __syncthreads();
    if (t == 0) {
        float mx = lg[0];
        for (int c2 = 1; c2 < NCLS; c2++) mx = fmaxf(mx, lg[c2]);
        float se = 0.f;
        for (int c2 = 0; c2 < NCLS; c2++) se += expf(lg[c2] - mx);
        float l = mx + logf(se);
        for (int c2 = 0; c2 < NCLS; c2++) out[g * NCLS + c2] = lg[c2] - l;
    }
}

// ---------------- host orchestration ---------------------------------------
static void run_gat_layer(const float* in_ptr, int fin,
                          const float* W, const float* a_s, const float* a_d,
                          const float* bias, const float* gam, const float* bet,
                          float* bufA)
{
    dim3 grid(W3 / BN, CDIV(NNODES, BM));
    gemm_kernel<<<grid, 256>>>(in_ptr, W, nullptr, bufA, NNODES, W3, fin, 0);
    attn_coef_kernel<<<CDIV(NNODES * NHEAD * 32, 256), 256>>>(a_s, a_d);
    gat_agg_kernel<<<CDIV(NNODES * 32, 256), 256>>>(bias);
    bn_zero_kernel<<<2, 256>>>();
    bn_reduce_kernel<<<512, 256>>>();
    bn_norm_kernel<<<2048, 256>>>(gam, bet);
}

extern "C" void kernel_launch(void* const* d_in, const int* in_sizes, int n_in,
                              void* d_out, int out_size)
{
    const float* x       = (const float*)d_in[0];
    const int*   ei      = (const int*)  d_in[1];
    const int*   batch   = (const int*)  d_in[2];
    const float* lin1_w  = (const float*)d_in[3];
    const float* lin1_b  = (const float*)d_in[4];
    const float* lin2_w  = (const float*)d_in[5];
    const float* lin2_b  = (const float*)d_in[6];
    const float* w0      = (const float*)d_in[7];
    const float* as0     = (const float*)d_in[8];
    const float* ad0     = (const float*)d_in[9];
    const float* b0      = (const float*)d_in[10];
    const float* wl      = (const float*)d_in[11];
    const float* asl     = (const float*)d_in[12];
    const float* adl     = (const float*)d_in[13];
    const float* bl      = (const float*)d_in[14];
    const float* gamma   = (const float*)d_in[15];
    const float* beta    = (const float*)d_in[16];
    const float* lin3_w  = (const float*)d_in[17];
    const float* lin3_b  = (const float*)d_in[18];
    const float* lin4_w  = (const float*)d_in[19];
    const float* lin4_b  = (const float*)d_in[20];
    float* out = (float*)d_out;

    float *bufA, *bufB;
    cudaGetSymbolAddress((void**)&bufA, g_bufA);
    cudaGetSymbolAddress((void**)&bufB, g_bufB);

    // ---- CSR build (dst-sorted adjacency), used by all 4 layers ----
    csr_zero_kernel<<<CDIV(NNODES, 256), 256>>>();
    csr_count_kernel<<<CDIV(ETOT, 256), 256>>>(ei);
    scan1_kernel<<<NBLK_SCAN, SCAN_B>>>();
    scan2_kernel<<<1, 512>>>();
    scan3_kernel<<<CDIV(NNODES, 256), 256>>>();
    csr_scatter_kernel<<<CDIV(ETOT, 256), 256>>>(ei);

    // ---- MLP stem ----
    {
        dim3 grid1(256 / BN, CDIV(NNODES, BM));
        gemm_kernel<<<grid1, 256>>>(x, lin1_w, lin1_b, bufA, NNODES, 2 * HID, F_IN, 1);
        dim3 grid2(HID / BN, CDIV(NNODES, BM));
        gemm_kernel<<<grid2, 256>>>(bufA, lin2_w, lin2_b, bufB, NNODES, HID, 2 * HID, 1);
    }

    // ---- GAT layer 0 (HID -> W3) ----
    run_gat_layer(bufB, HID, w0, as0, ad0, b0, gamma + 0 * W3, beta + 0 * W3, bufA);

    // ---- GAT layers 1..3 (W3 -> W3) ----
    for (int i = 0; i < NLAY - 1; i++) {
        run_gat_layer(bufB, W3,
                      wl + (size_t)i * W3 * W3,
                      asl + (size_t)i * NHEAD * HID,
                      adl + (size_t)i * NHEAD * HID,
                      bl + (size_t)i * W3,
                      gamma + (size_t)(i + 1) * W3,
                      beta + (size_t)(i + 1) * W3,
                      bufA);
    }

    // ---- global mean pool + head ----
    pool_zero_kernel<<<1024, 256>>>();
    pool_kernel<<<CDIV(NNODES * 32, 256), 256>>>(batch);
    head_kernel<<<NGRAPH, 128>>>(lin3_w, lin3_b, lin4_w, lin4_b, out);
}

// round 7
// speedup vs baseline: 2.4277x; 1.7890x over previous
#include <cuda_runtime.h>
#include <cuda_bf16.h>
#include <math.h>
#include <stdint.h>

// ---------------- problem constants ----------------
#define NNODES 100000
#define NEDGES 400000
#define ETOT   (NEDGES + NNODES)   // with self loops = 500000
#define NGRAPH 4000
#define F_IN   32
#define HID    128
#define NHEAD  3
#define W3     (NHEAD * HID)       // 384
#define NCLS   10
#define NLAY   4
#define NEG_SLOPE 0.2f

#define CDIV(a,b) (((a)+(b)-1)/(b))

#define SCAN_B 256
#define NBLK_SCAN CDIV(NNODES, SCAN_B)   // 391

// ---------------- scratch (device globals, no allocation) ----------------
__device__ float g_bufA[(size_t)NNODES * W3];   // GEMM output / Hw
__device__ float g_bufB[(size_t)NNODES * W3];   // layer in/out
__device__ float g_es[NNODES * NHEAD];
__device__ float g_ed[NNODES * NHEAD];
__device__ int   g_deg[NNODES];
__device__ int   g_off[NNODES + 1];
__device__ int   g_bsum[512];
__device__ int   g_cur[NNODES];
__device__ int   g_csr_src[ETOT];
__device__ float g_colsum[W3];
__device__ float g_colsq[W3];
__device__ float g_pool[(size_t)NGRAPH * W3];
__device__ float g_cnt[NGRAPH];

// ---------------- tf32 tensor-core GEMM ------------------------------------
// C[M,Nw] = A[M,K] @ B[K,Nw] (+bias, optional relu). fp32 in/out, tf32 mma.
// Block tile 128x128, BK=32. 8 warps, each 32x64 warp tile.
#define TBM 128
#define TBN 128
#define TBK 32
#define A_STRIDE 36   // BK + 4 pad
#define B_STRIDE 132  // BN + 4 pad

__device__ __forceinline__ uint32_t f2tf32(float v) {
    uint32_t t;
    asm("cvt.rna.tf32.f32 %0, %1;" : "=r"(t) : "f"(v));
    return t;
}

__global__ __launch_bounds__(256, 2)
void gemm_tf32_kernel(const float* __restrict__ A, const float* __restrict__ B,
                      const float* __restrict__ bias, float* __restrict__ C,
                      int M, int Nw, int K, int relu)
{
    __shared__ uint32_t As[TBM][A_STRIDE];   // [row][k]
    __shared__ uint32_t Bs[TBK][B_STRIDE];   // [k][col]

    const int bm = blockIdx.y * TBM;
    const int bn = blockIdx.x * TBN;
    const int tid  = threadIdx.x;            // 256
    const int lane = tid & 31;
    const int warp = tid >> 5;
    const int wm = warp & 3;                 // 0..3  -> rows wm*32
    const int wn = warp >> 2;                // 0..1  -> cols wn*64

    // loader indices
    const int a_r  = tid >> 3;               // 0..31
    const int a_c4 = (tid & 7) * 4;          // 0..28
    const int b_k  = tid >> 5;               // 0..7
    const int b_c4 = (tid & 31) * 4;         // 0..124

    float c[2][8][4];
#pragma unroll
    for (int mt = 0; mt < 2; mt++)
#pragma unroll
        for (int nt = 0; nt < 8; nt++)
#pragma unroll
            for (int r = 0; r < 4; r++) c[mt][nt][r] = 0.f;

    const int lq = lane >> 2;    // 0..7
    const int lr = lane & 3;     // 0..3

    for (int k0 = 0; k0 < K; k0 += TBK) {
        // load A tile: 128 x 32
#pragma unroll
        for (int i = 0; i < 4; i++) {
            int r = a_r + i * 32;
            int gr = bm + r;
            float4 v = make_float4(0.f, 0.f, 0.f, 0.f);
            if (gr < M)
                v = *reinterpret_cast<const float4*>(A + (size_t)gr * K + k0 + a_c4);
            uint4 t;
            t.x = f2tf32(v.x); t.y = f2tf32(v.y); t.z = f2tf32(v.z); t.w = f2tf32(v.w);
            *reinterpret_cast<uint4*>(&As[r][a_c4]) = t;
        }
        // load B tile: 32 x 128
#pragma unroll
        for (int i = 0; i < 4; i++) {
            int kr = b_k + i * 8;
            float4 v = *reinterpret_cast<const float4*>(B + (size_t)(k0 + kr) * Nw + bn + b_c4);
            uint4 t;
            t.x = f2tf32(v.x); t.y = f2tf32(v.y); t.z = f2tf32(v.z); t.w = f2tf32(v.w);
            *reinterpret_cast<uint4*>(&Bs[kr][b_c4]) = t;
        }
        __syncthreads();

#pragma unroll
        for (int kk = 0; kk < TBK; kk += 8) {
            // A fragments: 2 m-tiles
            uint32_t a[2][4];
#pragma unroll
            for (int mt = 0; mt < 2; mt++) {
                int row = wm * 32 + mt * 16 + lq;
                a[mt][0] = As[row][kk + lr];
                a[mt][1] = As[row + 8][kk + lr];
                a[mt][2] = As[row][kk + 4 + lr];
                a[mt][3] = As[row + 8][kk + 4 + lr];
            }
            // B fragments: 8 n-tiles
            uint32_t b[8][2];
#pragma unroll
            for (int nt = 0; nt < 8; nt++) {
                int col = wn * 64 + nt * 8 + lq;
                b[nt][0] = Bs[kk + lr][col];
                b[nt][1] = Bs[kk + 4 + lr][col];
            }
#pragma unroll
            for (int mt = 0; mt < 2; mt++)
#pragma unroll
                for (int nt = 0; nt < 8; nt++) {
                    asm volatile(
                        "mma.sync.aligned.m16n8k8.row.col.f32.tf32.tf32.f32 "
                        "{%0,%1,%2,%3}, {%4,%5,%6,%7}, {%8,%9}, {%0,%1,%2,%3};"
                        : "+f"(c[mt][nt][0]), "+f"(c[mt][nt][1]),
                          "+f"(c[mt][nt][2]), "+f"(c[mt][nt][3])
                        : "r"(a[mt][0]), "r"(a[mt][1]), "r"(a[mt][2]), "r"(a[mt][3]),
                          "r"(b[nt][0]), "r"(b[nt][1]));
                }
        }
        __syncthreads();
    }

    // epilogue
#pragma unroll
    for (int mt = 0; mt < 2; mt++) {
#pragma unroll
        for (int nt = 0; nt < 8; nt++) {
            int row0 = bm + wm * 32 + mt * 16 + lq;
            int col  = bn + wn * 64 + nt * 8 + lr * 2;
            float bx = 0.f, by = 0.f;
            if (bias) { bx = bias[col]; by = bias[col + 1]; }
            if (row0 < M) {
                float vx = c[mt][nt][0] + bx;
                float vy = c[mt][nt][1] + by;
                if (relu) { vx = fmaxf(vx, 0.f); vy = fmaxf(vy, 0.f); }
                *reinterpret_cast<float2*>(C + (size_t)row0 * Nw + col) = make_float2(vx, vy);
            }
            int row1 = row0 + 8;
            if (row1 < M) {
                float vx = c[mt][nt][2] + bx;
                float vy = c[mt][nt][3] + by;
                if (relu) { vx = fmaxf(vx, 0.f); vy = fmaxf(vy, 0.f); }
                *reinterpret_cast<float2*>(C + (size_t)row1 * Nw + col) = make_float2(vx, vy);
            }
        }
    }
}

// ---------------- CSR build ------------------------------------------------
__global__ void csr_zero_kernel()
{
    int i = blockIdx.x * blockDim.x + threadIdx.x;
    if (i < NNODES) { g_deg[i] = 0; g_cur[i] = 0; }
}

__global__ void csr_count_kernel(const int* __restrict__ ei)
{
    int i = blockIdx.x * blockDim.x + threadIdx.x;
    if (i >= ETOT) return;
    int d = (i < NEDGES) ? ei[NEDGES + i] : (i - NEDGES);
    atomicAdd(&g_deg[d], 1);
}

__global__ void scan1_kernel()
{
    __shared__ int sh[SCAN_B];
    int t = threadIdx.x;
    int i = blockIdx.x * SCAN_B + t;
    int v = (i < NNODES) ? g_deg[i] : 0;
    sh[t] = v;
    __syncthreads();
#pragma unroll
    for (int o = 1; o < SCAN_B; o <<= 1) {
        int x = (t >= o) ? sh[t - o] : 0;
        __syncthreads();
        sh[t] += x;
        __syncthreads();
    }
    if (i < NNODES) g_off[i] = sh[t] - v;           // exclusive within block
    if (t == SCAN_B - 1) g_bsum[blockIdx.x] = sh[t];
}

__global__ void scan2_kernel()
{
    __shared__ int sh[512];
    int t = threadIdx.x;  // 512 threads
    int v = (t < NBLK_SCAN) ? g_bsum[t] : 0;
    sh[t] = v;
    __syncthreads();
#pragma unroll
    for (int o = 1; o < 512; o <<= 1) {
        int x = (t >= o) ? sh[t - o] : 0;
        __syncthreads();
        sh[t] += x;
        __syncthreads();
    }
    if (t < NBLK_SCAN) g_bsum[t] = sh[t] - v;       // exclusive block offsets
}

__global__ void scan3_kernel()
{
    int i = blockIdx.x * blockDim.x + threadIdx.x;
    if (i < NNODES) g_off[i] += g_bsum[i / SCAN_B];
    if (i == 0) g_off[NNODES] = ETOT;
}

__global__ void csr_scatter_kernel(const int* __restrict__ ei)
{
    int i = blockIdx.x * blockDim.x + threadIdx.x;
    if (i >= ETOT) return;
    int s = (i < NEDGES) ? ei[i] : (i - NEDGES);
    int d = (i < NEDGES) ? ei[NEDGES + i] : (i - NEDGES);
    int pos = g_off[d] + atomicAdd(&g_cur[d], 1);
    g_csr_src[pos] = s;
}

// ---------------- attention coefficients: es/ed per (node, head) ----------
__global__ void attn_coef_kernel(const float* __restrict__ asrc, const float* __restrict__ adst)
{
    int gw = (blockIdx.x * blockDim.x + threadIdx.x) >> 5;
    int lane = threadIdx.x & 31;
    if (gw >= NNODES * NHEAD) return;
    int n = gw / NHEAD, h = gw % NHEAD;
    float4 v = reinterpret_cast<const float4*>(g_bufA + (size_t)n * W3 + h * HID)[lane];
    float4 a = reinterpret_cast<const float4*>(asrc + h * HID)[lane];
    float4 b = reinterpret_cast<const float4*>(adst + h * HID)[lane];
    float s = v.x * a.x + v.y * a.y + v.z * a.z + v.w * a.w;
    float d = v.x * b.x + v.y * b.y + v.z * b.z + v.w * b.w;
#pragma unroll
    for (int o = 16; o > 0; o >>= 1) {
        s += __shfl_down_sync(0xffffffffu, s, o);
        d += __shfl_down_sync(0xffffffffu, d, o);
    }
    if (lane == 0) { g_es[gw] = s; g_ed[gw] = d; }
}

// ---------------- fused segment-softmax + aggregation (warp per node) ------
__device__ __forceinline__ float lrelu(float x) {
    return (x > 0.f) ? x : NEG_SLOPE * x;
}

__global__ void gat_agg_kernel(const float* __restrict__ bias)
{
    int gw = (blockIdx.x * blockDim.x + threadIdx.x) >> 5;
    int lane = threadIdx.x & 31;
    if (gw >= NNODES) return;
    const int n = gw;
    const int off0 = g_off[n];
    const int off1 = g_off[n + 1];

    const float ed0 = g_ed[n * 3 + 0];
    const float ed1 = g_ed[n * 3 + 1];
    const float ed2 = g_ed[n * 3 + 2];

    // pass A1: per-head max over incoming edges (lanes split edges)
    float m0 = -1e30f, m1 = -1e30f, m2 = -1e30f;
    for (int e = off0 + lane; e < off1; e += 32) {
        int s = g_csr_src[e];
        m0 = fmaxf(m0, lrelu(g_es[s * 3 + 0] + ed0));
        m1 = fmaxf(m1, lrelu(g_es[s * 3 + 1] + ed1));
        m2 = fmaxf(m2, lrelu(g_es[s * 3 + 2] + ed2));
    }
#pragma unroll
    for (int o = 16; o > 0; o >>= 1) {
        m0 = fmaxf(m0, __shfl_xor_sync(0xffffffffu, m0, o));
        m1 = fmaxf(m1, __shfl_xor_sync(0xffffffffu, m1, o));
        m2 = fmaxf(m2, __shfl_xor_sync(0xffffffffu, m2, o));
    }
    // pass A2: sum of exp
    float s0 = 0.f, s1 = 0.f, s2 = 0.f;
    for (int e = off0 + lane; e < off1; e += 32) {
        int s = g_csr_src[e];
        s0 += __expf(lrelu(g_es[s * 3 + 0] + ed0) - m0);
        s1 += __expf(lrelu(g_es[s * 3 + 1] + ed1) - m1);
        s2 += __expf(lrelu(g_es[s * 3 + 2] + ed2) - m2);
    }
#pragma unroll
    for (int o = 16; o > 0; o >>= 1) {
        s0 += __shfl_xor_sync(0xffffffffu, s0, o);
        s1 += __shfl_xor_sync(0xffffffffu, s1, o);
        s2 += __shfl_xor_sync(0xffffffffu, s2, o);
    }
    const float r0 = 1.f / s0, r1 = 1.f / s1, r2 = 1.f / s2;

    // pass B: gather + weighted accumulate, lanes split the 384 features
    float acc[12];
#pragma unroll
    for (int j = 0; j < 12; j++) acc[j] = 0.f;

    for (int e = off0; e < off1; e++) {
        int s = g_csr_src[e];                       // broadcast load
        float a0 = __expf(lrelu(g_es[s * 3 + 0] + ed0) - m0) * r0;
        float a1 = __expf(lrelu(g_es[s * 3 + 1] + ed1) - m1) * r1;
        float a2 = __expf(lrelu(g_es[s * 3 + 2] + ed2) - m2) * r2;
        const float* hp = g_bufA + (size_t)s * W3;
#pragma unroll
        for (int j = 0; j < 12; j++) {
            float al = (j < 4) ? a0 : ((j < 8) ? a1 : a2);
            acc[j] = fmaf(al, hp[j * 32 + lane], acc[j]);
        }
    }
    float* op = g_bufB + (size_t)n * W3;
#pragma unroll
    for (int j = 0; j < 12; j++)
        op[j * 32 + lane] = acc[j] + bias[j * 32 + lane];
}

// ---------------- batchnorm -----------------------------------------------
__global__ void bn_zero_kernel()
{
    int i = blockIdx.x * blockDim.x + threadIdx.x;
    if (i < W3) { g_colsum[i] = 0.f; g_colsq[i] = 0.f; }
}

__global__ void bn_reduce_kernel()
{
    int warp = (blockIdx.x * blockDim.x + threadIdx.x) >> 5;
    int lane = threadIdx.x & 31;
    int nwarps = (gridDim.x * blockDim.x) >> 5;
    float s[12], q[12];
#pragma unroll
    for (int j = 0; j < 12; j++) { s[j] = 0.f; q[j] = 0.f; }
    for (int r = warp; r < NNODES; r += nwarps) {
        const float* row = g_bufB + (size_t)r * W3;
#pragma unroll
        for (int j = 0; j < 12; j++) {
            float v = row[lane + j * 32];
            s[j] += v; q[j] += v * v;
        }
    }
#pragma unroll
    for (int j = 0; j < 12; j++) {
        atomicAdd(&g_colsum[lane + j * 32], s[j]);
        atomicAdd(&g_colsq[lane + j * 32], q[j]);
    }
}

__global__ void bn_norm_kernel(const float* __restrict__ gam, const float* __restrict__ bet)
{
    int idx = blockIdx.x * blockDim.x + threadIdx.x;
    int total = NNODES * W3;
    const float invN = 1.f / (float)NNODES;
    for (; idx < total; idx += gridDim.x * blockDim.x) {
        int j = idx % W3;
        float mu = g_colsum[j] * invN;
        float var = g_colsq[j] * invN - mu * mu;
        g_bufB[idx] = (g_bufB[idx] - mu) * rsqrtf(var + 1e-5f) * gam[j] + bet[j];
    }
}

// ---------------- mean pool -------------------------------------------------
__global__ void pool_zero_kernel()
{
    int idx = blockIdx.x * blockDim.x + threadIdx.x;
    int total = NGRAPH * W3;
    for (; idx < total; idx += gridDim.x * blockDim.x) g_pool[idx] = 0.f;
    for (int i = blockIdx.x * blockDim.x + threadIdx.x; i < NGRAPH; i += gridDim.x * blockDim.x)
        g_cnt[i] = 0.f;
}

__global__ void pool_kernel(const int* __restrict__ batch)
{
    int gw = (blockIdx.x * blockDim.x + threadIdx.x) >> 5;
    int lane = threadIdx.x & 31;
    if (gw >= NNODES) return;
    int g = batch[gw];
    const float* row = g_bufB + (size_t)gw * W3;
#pragma unroll
    for (int j = 0; j < 12; j++)
        atomicAdd(&g_pool[(size_t)g * W3 + lane + j * 32], row[lane + j * 32]);
    if (lane == 0) atomicAdd(&g_cnt[g], 1.f);
}

// ---------------- head: mean, lin3+relu, lin4, log_softmax -----------------
__global__ void head_kernel(const float* __restrict__ w3, const float* __restrict__ b3,
                            const float* __restrict__ w4, const float* __restrict__ b4,
                            float* __restrict__ out)
{
    __shared__ float gv[W3];
    __shared__ float hid[HID];
    __shared__ float lg[NCLS];
    int g = blockIdx.x;
    int t = threadIdx.x;   // 128 threads
    float c = fmaxf(g_cnt[g], 1.f);
    for (int j = t; j < W3; j += 128) gv[j] = g_pool[(size_t)g * W3 + j] / c;
    __syncthreads();
    float acc = b3[t];
    for (int k = 0; k < W3; k++) acc += gv[k] * w3[k * HID + t];
    hid[t] = fmaxf(acc, 0.f);
    __syncthreads();
    if (t < NCLS) {
        float a = b4[t];
        for (int k = 0; k < HID; k++) a += hid[k] * w4[k * NCLS + t];
        lg[t] = a;
    }
    __syncthreads();
    if (t == 0) {
        float mx = lg[0];
        for (int c2 = 1; c2 < NCLS; c2++) mx = fmaxf(mx, lg[c2]);
        float se = 0.f;
        for (int c2 = 0; c2 < NCLS; c2++) se += expf(lg[c2] - mx);
        float l = mx + logf(se);
        for (int c2 = 0; c2 < NCLS; c2++) out[g * NCLS + c2] = lg[c2] - l;
    }
}

// ---------------- host orchestration ---------------------------------------
static inline void launch_gemm(const float* A, const float* B, const float* bias,
                               float* C, int M, int Nw, int K, int relu)
{
    dim3 grid(Nw / TBN, CDIV(M, TBM));
    gemm_tf32_kernel<<<grid, 256>>>(A, B, bias, C, M, Nw, K, relu);
}

static void run_gat_layer(const float* in_ptr, int fin,
                          const float* W, const float* a_s, const float* a_d,
                          const float* bias, const float* gam, const float* bet,
                          float* bufA)
{
    launch_gemm(in_ptr, W, nullptr, bufA, NNODES, W3, fin, 0);
    attn_coef_kernel<<<CDIV(NNODES * NHEAD * 32, 256), 256>>>(a_s, a_d);
    gat_agg_kernel<<<CDIV(NNODES * 32, 256), 256>>>(bias);
    bn_zero_kernel<<<2, 256>>>();
    bn_reduce_kernel<<<512, 256>>>();
    bn_norm_kernel<<<2048, 256>>>(gam, bet);
}

extern "C" void kernel_launch(void* const* d_in, const int* in_sizes, int n_in,
                              void* d_out, int out_size)
{
    const float* x       = (const float*)d_in[0];
    const int*   ei      = (const int*)  d_in[1];
    const int*   batch   = (const int*)  d_in[2];
    const float* lin1_w  = (const float*)d_in[3];
    const float* lin1_b  = (const float*)d_in[4];
    const float* lin2_w  = (const float*)d_in[5];
    const float* lin2_b  = (const float*)d_in[6];
    const float* w0      = (const float*)d_in[7];
    const float* as0     = (const float*)d_in[8];
    const float* ad0     = (const float*)d_in[9];
    const float* b0      = (const float*)d_in[10];
    const float* wl      = (const float*)d_in[11];
    const float* asl     = (const float*)d_in[12];
    const float* adl     = (const float*)d_in[13];
    const float* bl      = (const float*)d_in[14];
    const float* gamma   = (const float*)d_in[15];
    const float* beta    = (const float*)d_in[16];
    const float* lin3_w  = (const float*)d_in[17];
    const float* lin3_b  = (const float*)d_in[18];
    const float* lin4_w  = (const float*)d_in[19];
    const float* lin4_b  = (const float*)d_in[20];
    float* out = (float*)d_out;

    float *bufA, *bufB;
    cudaGetSymbolAddress((void**)&bufA, g_bufA);
    cudaGetSymbolAddress((void**)&bufB, g_bufB);

    // ---- CSR build (dst-sorted adjacency), used by all 4 layers ----
    csr_zero_kernel<<<CDIV(NNODES, 256), 256>>>();
    csr_count_kernel<<<CDIV(ETOT, 256), 256>>>(ei);
    scan1_kernel<<<NBLK_SCAN, SCAN_B>>>();
    scan2_kernel<<<1, 512>>>();
    scan3_kernel<<<CDIV(NNODES, 256), 256>>>();
    csr_scatter_kernel<<<CDIV(ETOT, 256), 256>>>(ei);

    // ---- MLP stem ----
    launch_gemm(x, lin1_w, lin1_b, bufA, NNODES, 2 * HID, F_IN, 1);
    launch_gemm(bufA, lin2_w, lin2_b, bufB, NNODES, HID, 2 * HID, 1);

    // ---- GAT layer 0 (HID -> W3) ----
    run_gat_layer(bufB, HID, w0, as0, ad0, b0, gamma + 0 * W3, beta + 0 * W3, bufA);

    // ---- GAT layers 1..3 (W3 -> W3) ----
    for (int i = 0; i < NLAY - 1; i++) {
        run_gat_layer(bufB, W3,
                      wl + (size_t)i * W3 * W3,
                      asl + (size_t)i * NHEAD * HID,
                      adl + (size_t)i * NHEAD * HID,
                      bl + (size_t)i * W3,
                      gamma + (size_t)(i + 1) * W3,
                      beta + (size_t)(i + 1) * W3,
                      bufA);
    }

    // ---- global mean pool + head ----
    pool_zero_kernel<<<1024, 256>>>();
    pool_kernel<<<CDIV(NNODES * 32, 256), 256>>>(batch);
    head_kernel<<<NGRAPH, 128>>>(lin3_w, lin3_b, lin4_w, lin4_b, out);
}

// round 8
// speedup vs baseline: 2.8005x; 1.1536x over previous
#include <cuda_runtime.h>
#include <cuda_bf16.h>
#include <math.h>
#include <stdint.h>

// ---------------- problem constants ----------------
#define NNODES 100000
#define NEDGES 400000
#define ETOT   (NEDGES + NNODES)   // with self loops = 500000
#define NGRAPH 4000
#define F_IN   32
#define HID    128
#define NHEAD  3
#define W3     (NHEAD * HID)       // 384
#define NCLS   10
#define NLAY   4
#define NEG_SLOPE 0.2f

#define CDIV(a,b) (((a)+(b)-1)/(b))

#define SCAN_B 256
#define NBLK_SCAN CDIV(NNODES, SCAN_B)   // 391

// ---------------- scratch (device globals, no allocation) ----------------
__device__ float g_bufA[(size_t)NNODES * W3];   // GEMM output / Hw
__device__ float g_bufB[(size_t)NNODES * W3];   // layer in/out (raw aggregation)
__device__ float g_es[NNODES * NHEAD];
__device__ float g_ed[NNODES * NHEAD];
__device__ int   g_deg[NNODES];
__device__ int   g_off[NNODES + 1];
__device__ int   g_bsum[512];
__device__ int   g_cur[NNODES];
__device__ int   g_csr_src[ETOT];
__device__ float g_colsum[W3];
__device__ float g_colsq[W3];
__device__ float g_s[W3];   // BN folded scale
__device__ float g_t[W3];   // BN folded shift
__device__ float g_pool[(size_t)NGRAPH * W3];
__device__ float g_cnt[NGRAPH];

// ---------------- tf32 tensor-core GEMM, cp.async double-buffered ----------
// C[M,Nw] = BN(A)[M,K] @ B[K,Nw] (+bias, optional relu).
// BN(A) = A*s[k] + t[k] applied per K-column at fragment load (s/t optional).
// Block tile 128x128, BK=32, 2-stage pipeline. 8 warps x (32x64) warp tiles.
#define TBM 128
#define TBN 128
#define TBK 32
#define A_STRIDE 36   // 32 + 4 pad (floats)
#define B_STRIDE 132  // 128 + 4 pad (floats)
#define A_TILE (TBM * A_STRIDE)
#define B_TILE (TBK * B_STRIDE)
#define GEMM_SMEM_FLOATS (2 * A_TILE + 2 * B_TILE + 2 * W3)
#define GEMM_SMEM_BYTES  (GEMM_SMEM_FLOATS * 4)

__device__ __forceinline__ void cp_async16(uint32_t saddr, const void* gptr, int szbytes) {
    asm volatile("cp.async.cg.shared.global [%0], [%1], 16, %2;\n"
                 :: "r"(saddr), "l"(gptr), "r"(szbytes));
}
__device__ __forceinline__ void cp_commit() {
    asm volatile("cp.async.commit_group;\n");
}
template <int N>
__device__ __forceinline__ void cp_wait() {
    asm volatile("cp.async.wait_group %0;\n" :: "n"(N));
}

__global__ __launch_bounds__(256, 2)
void gemm_tf32_kernel(const float* __restrict__ A, const float* __restrict__ B,
                      const float* __restrict__ bias, float* __restrict__ C,
                      int M, int Nw, int K, int relu,
                      const float* __restrict__ bn_s, const float* __restrict__ bn_t)
{
    extern __shared__ float smem_f[];
    float* As  = smem_f;                 // [2][TBM][A_STRIDE]
    float* Bs  = smem_f + 2 * A_TILE;    // [2][TBK][B_STRIDE]
    float* Ssh = smem_f + 2 * A_TILE + 2 * B_TILE;   // [W3]
    float* Tsh = Ssh + W3;                            // [W3]

    const int bm = blockIdx.y * TBM;
    const int bn = blockIdx.x * TBN;
    const int tid  = threadIdx.x;            // 256
    const int lane = tid & 31;
    const int warp = tid >> 5;
    const int wm = warp & 3;                 // rows wm*32
    const int wn = warp >> 2;                // cols wn*64
    const bool has_bn = (bn_s != nullptr);

    // loader indices
    const int a_r  = tid >> 3;               // 0..31
    const int a_c4 = (tid & 7) * 4;          // 0..28
    const int b_k  = tid >> 5;               // 0..7
    const int b_c4 = (tid & 31) * 4;         // 0..124

    // BN tables -> smem
    if (has_bn) {
        for (int k = tid; k < K; k += 256) { Ssh[k] = bn_s[k]; Tsh[k] = bn_t[k]; }
    }

    const int nk = K / TBK;

    // stage loader
    auto load_stage = [&](int it, int stage) {
        const int k0 = it * TBK;
        float* Asg = As + stage * A_TILE;
        float* Bsg = Bs + stage * B_TILE;
#pragma unroll
        for (int i = 0; i < 4; i++) {
            int r = a_r + i * 32;
            int gr = bm + r;
            uint32_t sa = (uint32_t)__cvta_generic_to_shared(&Asg[r * A_STRIDE + a_c4]);
            cp_async16(sa, A + (size_t)gr * K + k0 + a_c4, (gr < M) ? 16 : 0);
        }
#pragma unroll
        for (int i = 0; i < 4; i++) {
            int kr = b_k + i * 8;
            uint32_t sa = (uint32_t)__cvta_generic_to_shared(&Bsg[kr * B_STRIDE + b_c4]);
            cp_async16(sa, B + (size_t)(k0 + kr) * Nw + bn + b_c4, 16);
        }
        cp_commit();
    };

    float c[2][8][4];
#pragma unroll
    for (int mt = 0; mt < 2; mt++)
#pragma unroll
        for (int nt = 0; nt < 8; nt++)
#pragma unroll
            for (int r = 0; r < 4; r++) c[mt][nt][r] = 0.f;

    const int lq = lane >> 2;    // 0..7
    const int lr = lane & 3;     // 0..3

    load_stage(0, 0);

    for (int it = 0; it < nk; it++) {
        if (it + 1 < nk) {
            load_stage(it + 1, (it + 1) & 1);
            cp_wait<1>();
        } else {
            cp_wait<0>();
        }
        __syncthreads();

        const int stage = it & 1;
        const float* Asg = As + stage * A_TILE;
        const float* Bsg = Bs + stage * B_TILE;
        const int k0 = it * TBK;

#pragma unroll
        for (int kk = 0; kk < TBK; kk += 8) {
            float s0v = 1.f, t0v = 0.f, s1v = 1.f, t1v = 0.f;
            if (has_bn) {
                s0v = Ssh[k0 + kk + lr];     t0v = Tsh[k0 + kk + lr];
                s1v = Ssh[k0 + kk + 4 + lr]; t1v = Tsh[k0 + kk + 4 + lr];
            }
            uint32_t a[2][4];
#pragma unroll
            for (int mt = 0; mt < 2; mt++) {
                int row = wm * 32 + mt * 16 + lq;
                float f0 = Asg[row * A_STRIDE + kk + lr];
                float f1 = Asg[(row + 8) * A_STRIDE + kk + lr];
                float f2 = Asg[row * A_STRIDE + kk + 4 + lr];
                float f3 = Asg[(row + 8) * A_STRIDE + kk + 4 + lr];
                if (has_bn) {
                    f0 = fmaf(f0, s0v, t0v); f1 = fmaf(f1, s0v, t0v);
                    f2 = fmaf(f2, s1v, t1v); f3 = fmaf(f3, s1v, t1v);
                }
                a[mt][0] = __float_as_uint(f0);
                a[mt][1] = __float_as_uint(f1);
                a[mt][2] = __float_as_uint(f2);
                a[mt][3] = __float_as_uint(f3);
            }
            uint32_t b[8][2];
#pragma unroll
            for (int nt = 0; nt < 8; nt++) {
                int col = wn * 64 + nt * 8 + lq;
                b[nt][0] = __float_as_uint(Bsg[(kk + lr) * B_STRIDE + col]);
                b[nt][1] = __float_as_uint(Bsg[(kk + 4 + lr) * B_STRIDE + col]);
            }
#pragma unroll
            for (int mt = 0; mt < 2; mt++)
#pragma unroll
                for (int nt = 0; nt < 8; nt++) {
                    asm volatile(
                        "mma.sync.aligned.m16n8k8.row.col.f32.tf32.tf32.f32 "
                        "{%0,%1,%2,%3}, {%4,%5,%6,%7}, {%8,%9}, {%0,%1,%2,%3};"
                        : "+f"(c[mt][nt][0]), "+f"(c[mt][nt][1]),
                          "+f"(c[mt][nt][2]), "+f"(c[mt][nt][3])
                        : "r"(a[mt][0]), "r"(a[mt][1]), "r"(a[mt][2]), "r"(a[mt][3]),
                          "r"(b[nt][0]), "r"(b[nt][1]));
                }
        }
        __syncthreads();
    }

    // epilogue
#pragma unroll
    for (int mt = 0; mt < 2; mt++) {
#pragma unroll
        for (int nt = 0; nt < 8; nt++) {
            int row0 = bm + wm * 32 + mt * 16 + lq;
            int col  = bn + wn * 64 + nt * 8 + lr * 2;
            float bx = 0.f, by = 0.f;
            if (bias) { bx = bias[col]; by = bias[col + 1]; }
            if (row0 < M) {
                float vx = c[mt][nt][0] + bx;
                float vy = c[mt][nt][1] + by;
                if (relu) { vx = fmaxf(vx, 0.f); vy = fmaxf(vy, 0.f); }
                *reinterpret_cast<float2*>(C + (size_t)row0 * Nw + col) = make_float2(vx, vy);
            }
            int row1 = row0 + 8;
            if (row1 < M) {
                float vx = c[mt][nt][2] + bx;
                float vy = c[mt][nt][3] + by;
                if (relu) { vx = fmaxf(vx, 0.f); vy = fmaxf(vy, 0.f); }
                *reinterpret_cast<float2*>(C + (size_t)row1 * Nw + col) = make_float2(vx, vy);
            }
        }
    }
}

// ---------------- CSR build ------------------------------------------------
__global__ void csr_zero_kernel()
{
    int i = blockIdx.x * blockDim.x + threadIdx.x;
    if (i < NNODES) { g_deg[i] = 0; g_cur[i] = 0; }
}

__global__ void csr_count_kernel(const int* __restrict__ ei)
{
    int i = blockIdx.x * blockDim.x + threadIdx.x;
    if (i >= ETOT) return;
    int d = (i < NEDGES) ? ei[NEDGES + i] : (i - NEDGES);
    atomicAdd(&g_deg[d], 1);
}

__global__ void scan1_kernel()
{
    __shared__ int sh[SCAN_B];
    int t = threadIdx.x;
    int i = blockIdx.x * SCAN_B + t;
    int v = (i < NNODES) ? g_deg[i] : 0;
    sh[t] = v;
    __syncthreads();
#pragma unroll
    for (int o = 1; o < SCAN_B; o <<= 1) {
        int x = (t >= o) ? sh[t - o] : 0;
        __syncthreads();
        sh[t] += x;
        __syncthreads();
    }
    if (i < NNODES) g_off[i] = sh[t] - v;
    if (t == SCAN_B - 1) g_bsum[blockIdx.x] = sh[t];
}

__global__ void scan2_kernel()
{
    __shared__ int sh[512];
    int t = threadIdx.x;
    int v = (t < NBLK_SCAN) ? g_bsum[t] : 0;
    sh[t] = v;
    __syncthreads();
#pragma unroll
    for (int o = 1; o < 512; o <<= 1) {
        int x = (t >= o) ? sh[t - o] : 0;
        __syncthreads();
        sh[t] += x;
        __syncthreads();
    }
    if (t < NBLK_SCAN) g_bsum[t] = sh[t] - v;
}

__global__ void scan3_kernel()
{
    int i = blockIdx.x * blockDim.x + threadIdx.x;
    if (i < NNODES) g_off[i] += g_bsum[i / SCAN_B];
    if (i == 0) g_off[NNODES] = ETOT;
}

__global__ void csr_scatter_kernel(const int* __restrict__ ei)
{
    int i = blockIdx.x * blockDim.x + threadIdx.x;
    if (i >= ETOT) return;
    int s = (i < NEDGES) ? ei[i] : (i - NEDGES);
    int d = (i < NEDGES) ? ei[NEDGES + i] : (i - NEDGES);
    int pos = g_off[d] + atomicAdd(&g_cur[d], 1);
    g_csr_src[pos] = s;
}

// ---------------- attention coefficients: es/ed per (node, head) ----------
__global__ void attn_coef_kernel(const float* __restrict__ asrc, const float* __restrict__ adst)
{
    int gw = (blockIdx.x * blockDim.x + threadIdx.x) >> 5;
    int lane = threadIdx.x & 31;
    if (gw >= NNODES * NHEAD) return;
    int n = gw / NHEAD, h = gw % NHEAD;
    float4 v = reinterpret_cast<const float4*>(g_bufA + (size_t)n * W3 + h * HID)[lane];
    float4 a = reinterpret_cast<const float4*>(asrc + h * HID)[lane];
    float4 b = reinterpret_cast<const float4*>(adst + h * HID)[lane];
    float s = v.x * a.x + v.y * a.y + v.z * a.z + v.w * a.w;
    float d = v.x * b.x + v.y * b.y + v.z * b.z + v.w * b.w;
#pragma unroll
    for (int o = 16; o > 0; o >>= 1) {
        s += __shfl_down_sync(0xffffffffu, s, o);
        d += __shfl_down_sync(0xffffffffu, d, o);
    }
    if (lane == 0) { g_es[gw] = s; g_ed[gw] = d; }
}

// ---------------- zero BN accumulators ------------------------------------
__global__ void bn_zero_kernel()
{
    int i = blockIdx.x * blockDim.x + threadIdx.x;
    if (i < W3) { g_colsum[i] = 0.f; g_colsq[i] = 0.f; }
}

// ---------------- fused softmax + aggregation + BN stats (warp/node) -------
__device__ __forceinline__ float lrelu(float x) {
    return (x > 0.f) ? x : NEG_SLOPE * x;
}

__global__ __launch_bounds__(256)
void gat_agg_kernel(const float* __restrict__ bias)
{
    __shared__ float sh_sum[W3];
    __shared__ float sh_sq[W3];
    const int tid = threadIdx.x;
    for (int i = tid; i < W3; i += 256) { sh_sum[i] = 0.f; sh_sq[i] = 0.f; }
    __syncthreads();

    int gw = (blockIdx.x * 256 + tid) >> 5;
    int lane = tid & 31;
    if (gw < NNODES) {
        const int n = gw;
        const int off0 = g_off[n];
        const int off1 = g_off[n + 1];

        const float ed0 = g_ed[n * 3 + 0];
        const float ed1 = g_ed[n * 3 + 1];
        const float ed2 = g_ed[n * 3 + 2];

        float m0 = -1e30f, m1 = -1e30f, m2 = -1e30f;
        for (int e = off0 + lane; e < off1; e += 32) {
            int s = g_csr_src[e];
            m0 = fmaxf(m0, lrelu(g_es[s * 3 + 0] + ed0));
            m1 = fmaxf(m1, lrelu(g_es[s * 3 + 1] + ed1));
            m2 = fmaxf(m2, lrelu(g_es[s * 3 + 2] + ed2));
        }
#pragma unroll
        for (int o = 16; o > 0; o >>= 1) {
            m0 = fmaxf(m0, __shfl_xor_sync(0xffffffffu, m0, o));
            m1 = fmaxf(m1, __shfl_xor_sync(0xffffffffu, m1, o));
            m2 = fmaxf(m2, __shfl_xor_sync(0xffffffffu, m2, o));
        }
        float s0 = 0.f, s1 = 0.f, s2 = 0.f;
        for (int e = off0 + lane; e < off1; e += 32) {
            int s = g_csr_src[e];
            s0 += __expf(lrelu(g_es[s * 3 + 0] + ed0) - m0);
            s1 += __expf(lrelu(g_es[s * 3 + 1] + ed1) - m1);
            s2 += __expf(lrelu(g_es[s * 3 + 2] + ed2) - m2);
        }
#pragma unroll
        for (int o = 16; o > 0; o >>= 1) {
            s0 += __shfl_xor_sync(0xffffffffu, s0, o);
            s1 += __shfl_xor_sync(0xffffffffu, s1, o);
            s2 += __shfl_xor_sync(0xffffffffu, s2, o);
        }
        const float r0 = 1.f / s0, r1 = 1.f / s1, r2 = 1.f / s2;

        float acc[12];
#pragma unroll
        for (int j = 0; j < 12; j++) acc[j] = 0.f;

        for (int e = off0; e < off1; e++) {
            int s = g_csr_src[e];
            float a0 = __expf(lrelu(g_es[s * 3 + 0] + ed0) - m0) * r0;
            float a1 = __expf(lrelu(g_es[s * 3 + 1] + ed1) - m1) * r1;
            float a2 = __expf(lrelu(g_es[s * 3 + 2] + ed2) - m2) * r2;
            const float* hp = g_bufA + (size_t)s * W3;
#pragma unroll
            for (int j = 0; j < 12; j++) {
                float al = (j < 4) ? a0 : ((j < 8) ? a1 : a2);
                acc[j] = fmaf(al, hp[j * 32 + lane], acc[j]);
            }
        }
        float* op = g_bufB + (size_t)n * W3;
#pragma unroll
        for (int j = 0; j < 12; j++) {
            float v = acc[j] + bias[j * 32 + lane];
            op[j * 32 + lane] = v;
            atomicAdd(&sh_sum[j * 32 + lane], v);
            atomicAdd(&sh_sq[j * 32 + lane], v * v);
        }
    }
    __syncthreads();
    for (int i = tid; i < W3; i += 256) {
        atomicAdd(&g_colsum[i], sh_sum[i]);
        atomicAdd(&g_colsq[i], sh_sq[i]);
    }
}

// ---------------- BN finalize: stats + gamma/beta -> s,t --------------------
__global__ void bn_finalize_kernel(const float* __restrict__ gam, const float* __restrict__ bet)
{
    int k = blockIdx.x * blockDim.x + threadIdx.x;
    if (k >= W3) return;
    const float invN = 1.f / (float)NNODES;
    float mu = g_colsum[k] * invN;
    float var = g_colsq[k] * invN - mu * mu;
    float rs = rsqrtf(var + 1e-5f);
    float s = rs * gam[k];
    g_s[k] = s;
    g_t[k] = bet[k] - mu * s;
}

// ---------------- mean pool (applies final BN affine) ----------------------
__global__ void pool_zero_kernel()
{
    int idx = blockIdx.x * blockDim.x + threadIdx.x;
    int total = NGRAPH * W3;
    for (; idx < total; idx += gridDim.x * blockDim.x) g_pool[idx] = 0.f;
    for (int i = blockIdx.x * blockDim.x + threadIdx.x; i < NGRAPH; i += gridDim.x * blockDim.x)
        g_cnt[i] = 0.f;
}

__global__ void pool_kernel(const int* __restrict__ batch)
{
    int gw = (blockIdx.x * blockDim.x + threadIdx.x) >> 5;
    int lane = threadIdx.x & 31;
    if (gw >= NNODES) return;
    int g = batch[gw];
    const float* row = g_bufB + (size_t)gw * W3;
#pragma unroll
    for (int j = 0; j < 12; j++) {
        int c = lane + j * 32;
        float v = fmaf(row[c], g_s[c], g_t[c]);
        atomicAdd(&g_pool[(size_t)g * W3 + c], v);
    }
    if (lane == 0) atomicAdd(&g_cnt[g], 1.f);
}

// ---------------- head: mean, lin3+relu, lin4, log_softmax -----------------
__global__ void head_kernel(const float* __restrict__ w3, const float* __restrict__ b3,
                            const float* __restrict__ w4, const float* __restrict__ b4,
                            float* __restrict__ out)
{
    __shared__ float gv[W3];
    __shared__ float hid[HID];
    __shared__ float lg[NCLS];
    int g = blockIdx.x;
    int t = threadIdx.x;   // 128 threads
    float c = fmaxf(g_cnt[g], 1.f);
    for (int j = t; j < W3; j += 128) gv[j] = g_pool[(size_t)g * W3 + j] / c;
    __syncthreads();
    float acc = b3[t];
    for (int k = 0; k < W3; k++) acc += gv[k] * w3[k * HID + t];
    hid[t] = fmaxf(acc, 0.f);
    __syncthreads();
    if (t < NCLS) {
        float a = b4[t];
        for (int k = 0; k < HID; k++) a += hid[k] * w4[k * NCLS + t];
        lg[t] = a;
    }
    __syncthreads();
    if (t == 0) {
        float mx = lg[0];
        for (int c2 = 1; c2 < NCLS; c2++) mx = fmaxf(mx, lg[c2]);
        float se = 0.f;
        for (int c2 = 0; c2 < NCLS; c2++) se += expf(lg[c2] - mx);
        float l = mx + logf(se);
        for (int c2 = 0; c2 < NCLS; c2++) out[g * NCLS + c2] = lg[c2] - l;
    }
}

// ---------------- host orchestration ---------------------------------------
static inline void launch_gemm(const float* A, const float* B, const float* bias,
                               float* C, int M, int Nw, int K, int relu,
                               const float* bn_s, const float* bn_t)
{
    dim3 grid(Nw / TBN, CDIV(M, TBM));
    gemm_tf32_kernel<<<grid, 256, GEMM_SMEM_BYTES>>>(A, B, bias, C, M, Nw, K, relu, bn_s, bn_t);
}

extern "C" void kernel_launch(void* const* d_in, const int* in_sizes, int n_in,
                              void* d_out, int out_size)
{
    const float* x       = (const float*)d_in[0];
    const int*   ei      = (const int*)  d_in[1];
    const int*   batch   = (const int*)  d_in[2];
    const float* lin1_w  = (const float*)d_in[3];
    const float* lin1_b  = (const float*)d_in[4];
    const float* lin2_w  = (const float*)d_in[5];
    const float* lin2_b  = (const float*)d_in[6];
    const float* w0      = (const float*)d_in[7];
    const float* as0     = (const float*)d_in[8];
    const float* ad0     = (const float*)d_in[9];
    const float* b0      = (const float*)d_in[10];
    const float* wl      = (const float*)d_in[11];
    const float* asl     = (const float*)d_in[12];
    const float* adl     = (const float*)d_in[13];
    const float* bl      = (const float*)d_in[14];
    const float* gamma   = (const float*)d_in[15];
    const float* beta    = (const float*)d_in[16];
    const float* lin3_w  = (const float*)d_in[17];
    const float* lin3_b  = (const float*)d_in[18];
    const float* lin4_w  = (const float*)d_in[19];
    const float* lin4_b  = (const float*)d_in[20];
    float* out = (float*)d_out;

    static bool attr_set = false;
    if (!attr_set) {
        cudaFuncSetAttribute(gemm_tf32_kernel,
                             cudaFuncAttributeMaxDynamicSharedMemorySize, GEMM_SMEM_BYTES);
        attr_set = true;
    }

    float *bufA, *bufB, *sPtr, *tPtr;
    cudaGetSymbolAddress((void**)&bufA, g_bufA);
    cudaGetSymbolAddress((void**)&bufB, g_bufB);
    cudaGetSymbolAddress((void**)&sPtr, g_s);
    cudaGetSymbolAddress((void**)&tPtr, g_t);

    // ---- CSR build (dst-sorted adjacency), used by all 4 layers ----
    csr_zero_kernel<<<CDIV(NNODES, 256), 256>>>();
    csr_count_kernel<<<CDIV(ETOT, 256), 256>>>(ei);
    scan1_kernel<<<NBLK_SCAN, SCAN_B>>>();
    scan2_kernel<<<1, 512>>>();
    scan3_kernel<<<CDIV(NNODES, 256), 256>>>();
    csr_scatter_kernel<<<CDIV(ETOT, 256), 256>>>(ei);

    // ---- MLP stem (no BN on input) ----
    launch_gemm(x, lin1_w, lin1_b, bufA, NNODES, 2 * HID, F_IN, 1, nullptr, nullptr);
    launch_gemm(bufA, lin2_w, lin2_b, bufB, NNODES, HID, 2 * HID, 1, nullptr, nullptr);

    // ---- GAT layer 0 (input: stem output, no BN fold) ----
    launch_gemm(bufB, w0, nullptr, bufA, NNODES, W3, HID, 0, nullptr, nullptr);
    attn_coef_kernel<<<CDIV(NNODES * NHEAD * 32, 256), 256>>>(as0, ad0);
    bn_zero_kernel<<<2, 256>>>();
    gat_agg_kernel<<<CDIV(NNODES * 32, 256), 256>>>(b0);
    bn_finalize_kernel<<<2, 256>>>(gamma + 0 * W3, beta + 0 * W3);

    // ---- GAT layers 1..3 (BN of previous layer folded into GEMM A-load) ----
    for (int i = 0; i < NLAY - 1; i++) {
        const float* W  = wl  + (size_t)i * W3 * W3;
        const float* aS = asl + (size_t)i * NHEAD * HID;
        const float* aD = adl + (size_t)i * NHEAD * HID;
        const float* bb = bl  + (size_t)i * W3;
        launch_gemm(bufB, W, nullptr, bufA, NNODES, W3, W3, 0, sPtr, tPtr);
        attn_coef_kernel<<<CDIV(NNODES * NHEAD * 32, 256), 256>>>(aS, aD);
        bn_zero_kernel<<<2, 256>>>();
        gat_agg_kernel<<<CDIV(NNODES * 32, 256), 256>>>(bb);
        bn_finalize_kernel<<<2, 256>>>(gamma + (size_t)(i + 1) * W3, beta + (size_t)(i + 1) * W3);
    }

    // ---- global mean pool (applies final BN affine) + head ----
    pool_zero_kernel<<<1024, 256>>>();
    pool_kernel<<<CDIV(NNODES * 32, 256), 256>>>(batch);
    head_kernel<<<NGRAPH, 128>>>(lin3_w, lin3_b, lin4_w, lin4_b, out);
}

// round 9
// speedup vs baseline: 2.9095x; 1.0389x over previous
#include <cuda_runtime.h>
#include <cuda_bf16.h>
#include <math.h>
#include <stdint.h>

// ---------------- problem constants ----------------
#define NNODES 100000
#define NEDGES 400000
#define ETOT   (NEDGES + NNODES)   // with self loops = 500000
#define NGRAPH 4000
#define F_IN   32
#define HID    128
#define NHEAD  3
#define W3     (NHEAD * HID)       // 384
#define NCLS   10
#define NLAY   4
#define NEG_SLOPE 0.2f

#define CDIV(a,b) (((a)+(b)-1)/(b))

#define SCAN_B 256
#define NBLK_SCAN CDIV(NNODES, SCAN_B)   // 391

// ---------------- scratch (device globals, no allocation) ----------------
__device__ float g_bufA[(size_t)NNODES * W3];   // GEMM output / Hw
__device__ float g_bufB[(size_t)NNODES * W3];   // layer in/out (raw aggregation)
__device__ float g_es[NNODES * NHEAD];
__device__ float g_ed[NNODES * NHEAD];
__device__ int   g_deg[NNODES];
__device__ int   g_off[NNODES + 1];
__device__ int   g_bsum[512];
__device__ int   g_cur[NNODES];
__device__ int   g_csr_src[ETOT];
__device__ float g_colsum[W3];
__device__ float g_colsq[W3];
__device__ float g_s[W3];   // BN folded scale
__device__ float g_t[W3];   // BN folded shift
__device__ float g_pool[(size_t)NGRAPH * W3];
__device__ float g_cnt[NGRAPH];

// ---------------- tf32 tensor-core GEMM, cp.async 3-stage pipeline ---------
// C[M,Nw] = BN(A)[M,K] @ B[K,Nw] (+bias, optional relu).
// BN(A) = A*s[k] + t[k] applied per K-column at fragment load (optional).
// If attn: also emits g_es/g_ed for the block's head (requires Nw==W3,TBN==128).
#define TBM 128
#define TBN 128
#define TBK 32
#define NSTAGE 3
#define A_STRIDE 36   // 32 + 4 pad (floats)
#define B_STRIDE 132  // 128 + 4 pad (floats)
#define A_TILE (TBM * A_STRIDE)
#define B_TILE (TBK * B_STRIDE)
#define GEMM_SMEM_FLOATS (NSTAGE * A_TILE + NSTAGE * B_TILE + 2 * W3 + 2 * TBN + 2 * TBM)
#define GEMM_SMEM_BYTES  (GEMM_SMEM_FLOATS * 4)

__device__ __forceinline__ void cp_async16(uint32_t saddr, const void* gptr, int szbytes) {
    asm volatile("cp.async.cg.shared.global [%0], [%1], 16, %2;\n"
                 :: "r"(saddr), "l"(gptr), "r"(szbytes));
}
__device__ __forceinline__ void cp_commit() {
    asm volatile("cp.async.commit_group;\n");
}
template <int N>
__device__ __forceinline__ void cp_wait() {
    asm volatile("cp.async.wait_group %0;\n" :: "n"(N));
}

__global__ __launch_bounds__(256, 2)
void gemm_tf32_kernel(const float* __restrict__ A, const float* __restrict__ B,
                      const float* __restrict__ bias, float* __restrict__ C,
                      int M, int Nw, int K, int relu,
                      const float* __restrict__ bn_s, const float* __restrict__ bn_t,
                      const float* __restrict__ asrc, const float* __restrict__ adst)
{
    extern __shared__ float smem_f[];
    float* As  = smem_f;                       // [NSTAGE][TBM][A_STRIDE]
    float* Bs  = As + NSTAGE * A_TILE;         // [NSTAGE][TBK][B_STRIDE]
    float* Ssh = Bs + NSTAGE * B_TILE;         // [W3]
    float* Tsh = Ssh + W3;                     // [W3]
    float* Asr = Tsh + W3;                     // [TBN] a_src slice for this head
    float* Adt = Asr + TBN;                    // [TBN]
    float* Esh = Adt + TBN;                    // [TBM] es accum
    float* Dsh = Esh + TBM;                    // [TBM] ed accum

    const int bm = blockIdx.y * TBM;
    const int bn = blockIdx.x * TBN;
    const int tid  = threadIdx.x;            // 256
    const int lane = tid & 31;
    const int warp = tid >> 5;
    const int wm = warp & 3;                 // rows wm*32
    const int wn = warp >> 2;                // cols wn*64
    const bool has_bn = (bn_s != nullptr);
    const bool has_attn = (asrc != nullptr);

    // loader indices
    const int a_r  = tid >> 3;               // 0..31
    const int a_c4 = (tid & 7) * 4;          // 0..28
    const int b_k  = tid >> 5;               // 0..7
    const int b_c4 = (tid & 31) * 4;         // 0..124

    if (has_bn)
        for (int k = tid; k < K; k += 256) { Ssh[k] = bn_s[k]; Tsh[k] = bn_t[k]; }
    if (has_attn) {
        // this block covers exactly one head: head = bn / HID
        const int head = bn / HID;
        if (tid < TBN) {
            Asr[tid] = asrc[head * HID + tid];
            Adt[tid] = adst[head * HID + tid];
        } else if (tid < TBN + TBM) {
            Esh[tid - TBN] = 0.f;
            Dsh[tid - TBN] = 0.f;
        }
    }

    const int nk = K / TBK;

    auto load_stage = [&](int it, int stage) {
        const int k0 = it * TBK;
        float* Asg = As + stage * A_TILE;
        float* Bsg = Bs + stage * B_TILE;
#pragma unroll
        for (int i = 0; i < 4; i++) {
            int r = a_r + i * 32;
            int gr = bm + r;
            uint32_t sa = (uint32_t)__cvta_generic_to_shared(&Asg[r * A_STRIDE + a_c4]);
            cp_async16(sa, A + (size_t)gr * K + k0 + a_c4, (gr < M) ? 16 : 0);
        }
#pragma unroll
        for (int i = 0; i < 4; i++) {
            int kr = b_k + i * 8;
            uint32_t sa = (uint32_t)__cvta_generic_to_shared(&Bsg[kr * B_STRIDE + b_c4]);
            cp_async16(sa, B + (size_t)(k0 + kr) * Nw + bn + b_c4, 16);
        }
        cp_commit();
    };

    float c[2][8][4];
#pragma unroll
    for (int mt = 0; mt < 2; mt++)
#pragma unroll
        for (int nt = 0; nt < 8; nt++)
#pragma unroll
            for (int r = 0; r < 4; r++) c[mt][nt][r] = 0.f;

    const int lq = lane >> 2;    // 0..7
    const int lr = lane & 3;     // 0..3

    load_stage(0, 0);
    if (nk > 1) load_stage(1, 1);

    for (int it = 0; it < nk; it++) {
        // ensure stage `it` is resident; keep up to 2 younger groups in flight
        if (it + 2 < nk) {
            load_stage(it + 2, (it + 2) % NSTAGE);
            cp_wait<2>();
        } else {
            int rem = nk - 1 - it;
            if (rem >= 2)      cp_wait<2>();
            else if (rem == 1) cp_wait<1>();
            else               cp_wait<0>();
        }
        __syncthreads();

        const int stage = it % NSTAGE;
        const float* Asg = As + stage * A_TILE;
        const float* Bsg = Bs + stage * B_TILE;
        const int k0 = it * TBK;

#pragma unroll
        for (int kk = 0; kk < TBK; kk += 8) {
            float s0v = 1.f, t0v = 0.f, s1v = 1.f, t1v = 0.f;
            if (has_bn) {
                s0v = Ssh[k0 + kk + lr];     t0v = Tsh[k0 + kk + lr];
                s1v = Ssh[k0 + kk + 4 + lr]; t1v = Tsh[k0 + kk + 4 + lr];
            }
            uint32_t a[2][4];
#pragma unroll
            for (int mt = 0; mt < 2; mt++) {
                int row = wm * 32 + mt * 16 + lq;
                float f0 = Asg[row * A_STRIDE + kk + lr];
                float f1 = Asg[(row + 8) * A_STRIDE + kk + lr];
                float f2 = Asg[row * A_STRIDE + kk + 4 + lr];
                float f3 = Asg[(row + 8) * A_STRIDE + kk + 4 + lr];
                if (has_bn) {
                    f0 = fmaf(f0, s0v, t0v); f1 = fmaf(f1, s0v, t0v);
                    f2 = fmaf(f2, s1v, t1v); f3 = fmaf(f3, s1v, t1v);
                }
                a[mt][0] = __float_as_uint(f0);
                a[mt][1] = __float_as_uint(f1);
                a[mt][2] = __float_as_uint(f2);
                a[mt][3] = __float_as_uint(f3);
            }
            uint32_t b[8][2];
#pragma unroll
            for (int nt = 0; nt < 8; nt++) {
                int col = wn * 64 + nt * 8 + lq;
                b[nt][0] = __float_as_uint(Bsg[(kk + lr) * B_STRIDE + col]);
                b[nt][1] = __float_as_uint(Bsg[(kk + 4 + lr) * B_STRIDE + col]);
            }
#pragma unroll
            for (int mt = 0; mt < 2; mt++)
#pragma unroll
                for (int nt = 0; nt < 8; nt++) {
                    asm volatile(
                        "mma.sync.aligned.m16n8k8.row.col.f32.tf32.tf32.f32 "
                        "{%0,%1,%2,%3}, {%4,%5,%6,%7}, {%8,%9}, {%0,%1,%2,%3};"
                        : "+f"(c[mt][nt][0]), "+f"(c[mt][nt][1]),
                          "+f"(c[mt][nt][2]), "+f"(c[mt][nt][3])
                        : "r"(a[mt][0]), "r"(a[mt][1]), "r"(a[mt][2]), "r"(a[mt][3]),
                          "r"(b[nt][0]), "r"(b[nt][1]));
                }
        }
        __syncthreads();
    }

    // epilogue: store C; optionally accumulate es/ed per row
    float es_p[2][2] = {{0.f, 0.f}, {0.f, 0.f}};   // [mt][row-half]
    float ed_p[2][2] = {{0.f, 0.f}, {0.f, 0.f}};

#pragma unroll
    for (int mt = 0; mt < 2; mt++) {
#pragma unroll
        for (int nt = 0; nt < 8; nt++) {
            int row0 = bm + wm * 32 + mt * 16 + lq;
            int lcol = wn * 64 + nt * 8 + lr * 2;
            int col  = bn + lcol;
            float bx = 0.f, by = 0.f;
            if (bias) { bx = bias[col]; by = bias[col + 1]; }
            float v0x = c[mt][nt][0] + bx, v0y = c[mt][nt][1] + by;
            float v1x = c[mt][nt][2] + bx, v1y = c[mt][nt][3] + by;
            if (relu) {
                v0x = fmaxf(v0x, 0.f); v0y = fmaxf(v0y, 0.f);
                v1x = fmaxf(v1x, 0.f); v1y = fmaxf(v1y, 0.f);
            }
            if (row0 < M)
                *reinterpret_cast<float2*>(C + (size_t)row0 * Nw + col) = make_float2(v0x, v0y);
            if (row0 + 8 < M)
                *reinterpret_cast<float2*>(C + (size_t)(row0 + 8) * Nw + col) = make_float2(v1x, v1y);
            if (has_attn) {
                float ax = Asr[lcol], ay = Asr[lcol + 1];
                float dx = Adt[lcol], dy = Adt[lcol + 1];
                es_p[mt][0] += v0x * ax + v0y * ay;
                ed_p[mt][0] += v0x * dx + v0y * dy;
                es_p[mt][1] += v1x * ax + v1y * ay;
                ed_p[mt][1] += v1x * dx + v1y * dy;
            }
        }
    }

    if (has_attn) {
        // reduce over lr (lanes 4*lq + lr share the same rows)
#pragma unroll
        for (int mt = 0; mt < 2; mt++)
#pragma unroll
            for (int rh = 0; rh < 2; rh++) {
#pragma unroll
                for (int o = 1; o < 4; o <<= 1) {
                    es_p[mt][rh] += __shfl_xor_sync(0xffffffffu, es_p[mt][rh], o);
                    ed_p[mt][rh] += __shfl_xor_sync(0xffffffffu, ed_p[mt][rh], o);
                }
            }
        if (lr == 0) {
#pragma unroll
            for (int mt = 0; mt < 2; mt++)
#pragma unroll
                for (int rh = 0; rh < 2; rh++) {
                    int rloc = wm * 32 + mt * 16 + rh * 8 + lq;
                    atomicAdd(&Esh[rloc], es_p[mt][rh]);   // 2 warps (wn) per row
                    atomicAdd(&Dsh[rloc], ed_p[mt][rh]);
                }
        }
        __syncthreads();
        const int head = bn / HID;
        if (tid < TBM) {
            int row = bm + tid;
            if (row < M) {
                g_es[row * NHEAD + head] = Esh[tid];
                g_ed[row * NHEAD + head] = Dsh[tid];
            }
        }
    }
}

// ---------------- CSR build ------------------------------------------------
__global__ void csr_zero_kernel()
{
    int i = blockIdx.x * blockDim.x + threadIdx.x;
    if (i < NNODES) { g_deg[i] = 0; g_cur[i] = 0; }
}

__global__ void csr_count_kernel(const int* __restrict__ ei)
{
    int i = blockIdx.x * blockDim.x + threadIdx.x;
    if (i >= ETOT) return;
    int d = (i < NEDGES) ? ei[NEDGES + i] : (i - NEDGES);
    atomicAdd(&g_deg[d], 1);
}

__global__ void scan1_kernel()
{
    __shared__ int sh[SCAN_B];
    int t = threadIdx.x;
    int i = blockIdx.x * SCAN_B + t;
    int v = (i < NNODES) ? g_deg[i] : 0;
    sh[t] = v;
    __syncthreads();
#pragma unroll
    for (int o = 1; o < SCAN_B; o <<= 1) {
        int x = (t >= o) ? sh[t - o] : 0;
        __syncthreads();
        sh[t] += x;
        __syncthreads();
    }
    if (i < NNODES) g_off[i] = sh[t] - v;
    if (t == SCAN_B - 1) g_bsum[blockIdx.x] = sh[t];
}

__global__ void scan2_kernel()
{
    __shared__ int sh[512];
    int t = threadIdx.x;
    int v = (t < NBLK_SCAN) ? g_bsum[t] : 0;
    sh[t] = v;
    __syncthreads();
#pragma unroll
    for (int o = 1; o < 512; o <<= 1) {
        int x = (t >= o) ? sh[t - o] : 0;
        __syncthreads();
        sh[t] += x;
        __syncthreads();
    }
    if (t < NBLK_SCAN) g_bsum[t] = sh[t] - v;
}

__global__ void scan3_kernel()
{
    int i = blockIdx.x * blockDim.x + threadIdx.x;
    if (i < NNODES) g_off[i] += g_bsum[i / SCAN_B];
    if (i == 0) g_off[NNODES] = ETOT;
}

__global__ void csr_scatter_kernel(const int* __restrict__ ei)
{
    int i = blockIdx.x * blockDim.x + threadIdx.x;
    if (i >= ETOT) return;
    int s = (i < NEDGES) ? ei[i] : (i - NEDGES);
    int d = (i < NEDGES) ? ei[NEDGES + i] : (i - NEDGES);
    int pos = g_off[d] + atomicAdd(&g_cur[d], 1);
    g_csr_src[pos] = s;
}

// ---------------- zero BN accumulators ------------------------------------
__global__ void bn_zero_kernel()
{
    int i = blockIdx.x * blockDim.x + threadIdx.x;
    if (i < W3) { g_colsum[i] = 0.f; g_colsq[i] = 0.f; }
}

// ---------------- fused softmax + aggregation + BN stats (warp/node) -------
__device__ __forceinline__ float lrelu(float x) {
    return (x > 0.f) ? x : NEG_SLOPE * x;
}

__global__ __launch_bounds__(256)
void gat_agg_kernel(const float* __restrict__ bias)
{
    __shared__ float sh_sum[W3];
    __shared__ float sh_sq[W3];
    const int tid = threadIdx.x;
    for (int i = tid; i < W3; i += 256) { sh_sum[i] = 0.f; sh_sq[i] = 0.f; }
    __syncthreads();

    int gw = (blockIdx.x * 256 + tid) >> 5;
    int lane = tid & 31;
    if (gw < NNODES) {
        const int n = gw;
        const int off0 = g_off[n];
        const int off1 = g_off[n + 1];

        const float ed0 = g_ed[n * 3 + 0];
        const float ed1 = g_ed[n * 3 + 1];
        const float ed2 = g_ed[n * 3 + 2];

        float m0 = -1e30f, m1 = -1e30f, m2 = -1e30f;
        for (int e = off0 + lane; e < off1; e += 32) {
            int s = g_csr_src[e];
            m0 = fmaxf(m0, lrelu(g_es[s * 3 + 0] + ed0));
            m1 = fmaxf(m1, lrelu(g_es[s * 3 + 1] + ed1));
            m2 = fmaxf(m2, lrelu(g_es[s * 3 + 2] + ed2));
        }
#pragma unroll
        for (int o = 16; o > 0; o >>= 1) {
            m0 = fmaxf(m0, __shfl_xor_sync(0xffffffffu, m0, o));
            m1 = fmaxf(m1, __shfl_xor_sync(0xffffffffu, m1, o));
            m2 = fmaxf(m2, __shfl_xor_sync(0xffffffffu, m2, o));
        }
        float s0 = 0.f, s1 = 0.f, s2 = 0.f;
        for (int e = off0 + lane; e < off1; e += 32) {
            int s = g_csr_src[e];
            s0 += __expf(lrelu(g_es[s * 3 + 0] + ed0) - m0);
            s1 += __expf(lrelu(g_es[s * 3 + 1] + ed1) - m1);
            s2 += __expf(lrelu(g_es[s * 3 + 2] + ed2) - m2);
        }
#pragma unroll
        for (int o = 16; o > 0; o >>= 1) {
            s0 += __shfl_xor_sync(0xffffffffu, s0, o);
            s1 += __shfl_xor_sync(0xffffffffu, s1, o);
            s2 += __shfl_xor_sync(0xffffffffu, s2, o);
        }
        const float r0 = 1.f / s0, r1 = 1.f / s1, r2 = 1.f / s2;

        float acc[12];
#pragma unroll
        for (int j = 0; j < 12; j++) acc[j] = 0.f;

        for (int e = off0; e < off1; e++) {
            int s = g_csr_src[e];
            float a0 = __expf(lrelu(g_es[s * 3 + 0] + ed0) - m0) * r0;
            float a1 = __expf(lrelu(g_es[s * 3 + 1] + ed1) - m1) * r1;
            float a2 = __expf(lrelu(g_es[s * 3 + 2] + ed2) - m2) * r2;
            const float* hp = g_bufA + (size_t)s * W3;
#pragma unroll
            for (int j = 0; j < 12; j++) {
                float al = (j < 4) ? a0 : ((j < 8) ? a1 : a2);
                acc[j] = fmaf(al, hp[j * 32 + lane], acc[j]);
            }
        }
        float* op = g_bufB + (size_t)n * W3;
#pragma unroll
        for (int j = 0; j < 12; j++) {
            float v = acc[j] + bias[j * 32 + lane];
            op[j * 32 + lane] = v;
            atomicAdd(&sh_sum[j * 32 + lane], v);
            atomicAdd(&sh_sq[j * 32 + lane], v * v);
        }
    }
    __syncthreads();
    for (int i = tid; i < W3; i += 256) {
        atomicAdd(&g_colsum[i], sh_sum[i]);
        atomicAdd(&g_colsq[i], sh_sq[i]);
    }
}

// ---------------- BN finalize: stats + gamma/beta -> s,t --------------------
__global__ void bn_finalize_kernel(const float* __restrict__ gam, const float* __restrict__ bet)
{
    int k = blockIdx.x * blockDim.x + threadIdx.x;
    if (k >= W3) return;
    const float invN = 1.f / (float)NNODES;
    float mu = g_colsum[k] * invN;
    float var = g_colsq[k] * invN - mu * mu;
    float rs = rsqrtf(var + 1e-5f);
    float s = rs * gam[k];
    g_s[k] = s;
    g_t[k] = bet[k] - mu * s;
}

// ---------------- mean pool (applies final BN affine) ----------------------
__global__ void pool_zero_kernel()
{
    int idx = blockIdx.x * blockDim.x + threadIdx.x;
    int total = NGRAPH * W3;
    for (; idx < total; idx += gridDim.x * blockDim.x) g_pool[idx] = 0.f;
    for (int i = blockIdx.x * blockDim.x + threadIdx.x; i < NGRAPH; i += gridDim.x * blockDim.x)
        g_cnt[i] = 0.f;
}

__global__ void pool_kernel(const int* __restrict__ batch)
{
    int gw = (blockIdx.x * blockDim.x + threadIdx.x) >> 5;
    int lane = threadIdx.x & 31;
    if (gw >= NNODES) return;
    int g = batch[gw];
    const float* row = g_bufB + (size_t)gw * W3;
#pragma unroll
    for (int j = 0; j < 12; j++) {
        int c = lane + j * 32;
        float v = fmaf(row[c], g_s[c], g_t[c]);
        atomicAdd(&g_pool[(size_t)g * W3 + c], v);
    }
    if (lane == 0) atomicAdd(&g_cnt[g], 1.f);
}

// ---------------- head: mean, lin3+relu, lin4, log_softmax -----------------
__global__ void head_kernel(const float* __restrict__ w3, const float* __restrict__ b3,
                            const float* __restrict__ w4, const float* __restrict__ b4,
                            float* __restrict__ out)
{
    __shared__ float gv[W3];
    __shared__ float hid[HID];
    __shared__ float lg[NCLS];
    int g = blockIdx.x;
    int t = threadIdx.x;   // 128 threads
    float c = fmaxf(g_cnt[g], 1.f);
    for (int j = t; j < W3; j += 128) gv[j] = g_pool[(size_t)g * W3 + j] / c;
    __syncthreads();
    float acc = b3[t];
    for (int k = 0; k < W3; k++) acc += gv[k] * w3[k * HID + t];
    hid[t] = fmaxf(acc, 0.f);
    __syncthreads();
    if (t < NCLS) {
        float a = b4[t];
        for (int k = 0; k < HID; k++) a += hid[k] * w4[k * NCLS + t];
        lg[t] = a;
    }
    __syncthreads();
    if (t == 0) {
        float mx = lg[0];
        for (int c2 = 1; c2 < NCLS; c2++) mx = fmaxf(mx, lg[c2]);
        float se = 0.f;
        for (int c2 = 0; c2 < NCLS; c2++) se += expf(lg[c2] - mx);
        float l = mx + logf(se);
        for (int c2 = 0; c2 < NCLS; c2++) out[g * NCLS + c2] = lg[c2] - l;
    }
}

// ---------------- host orchestration ---------------------------------------
static inline void launch_gemm(const float* A, const float* B, const float* bias,
                               float* C, int M, int Nw, int K, int relu,
                               const float* bn_s, const float* bn_t,
                               const float* asrc, const float* adst)
{
    dim3 grid(Nw / TBN, CDIV(M, TBM));
    gemm_tf32_kernel<<<grid, 256, GEMM_SMEM_BYTES>>>(A, B, bias, C, M, Nw, K, relu,
                                                     bn_s, bn_t, asrc, adst);
}

extern "C" void kernel_launch(void* const* d_in, const int* in_sizes, int n_in,
                              void* d_out, int out_size)
{
    const float* x       = (const float*)d_in[0];
    const int*   ei      = (const int*)  d_in[1];
    const int*   batch   = (const int*)  d_in[2];
    const float* lin1_w  = (const float*)d_in[3];
    const float* lin1_b  = (const float*)d_in[4];
    const float* lin2_w  = (const float*)d_in[5];
    const float* lin2_b  = (const float*)d_in[6];
    const float* w0      = (const float*)d_in[7];
    const float* as0     = (const float*)d_in[8];
    const float* ad0     = (const float*)d_in[9];
    const float* b0      = (const float*)d_in[10];
    const float* wl      = (const float*)d_in[11];
    const float* asl     = (const float*)d_in[12];
    const float* adl     = (const float*)d_in[13];
    const float* bl      = (const float*)d_in[14];
    const float* gamma   = (const float*)d_in[15];
    const float* beta    = (const float*)d_in[16];
    const float* lin3_w  = (const float*)d_in[17];
    const float* lin3_b  = (const float*)d_in[18];
    const float* lin4_w  = (const float*)d_in[19];
    const float* lin4_b  = (const float*)d_in[20];
    float* out = (float*)d_out;

    static bool attr_set = false;
    if (!attr_set) {
        cudaFuncSetAttribute(gemm_tf32_kernel,
                             cudaFuncAttributeMaxDynamicSharedMemorySize, GEMM_SMEM_BYTES);
        attr_set = true;
    }

    float *bufA, *bufB, *sPtr, *tPtr;
    cudaGetSymbolAddress((void**)&bufA, g_bufA);
    cudaGetSymbolAddress((void**)&bufB, g_bufB);
    cudaGetSymbolAddress((void**)&sPtr, g_s);
    cudaGetSymbolAddress((void**)&tPtr, g_t);

    // ---- CSR build (dst-sorted adjacency), used by all 4 layers ----
    csr_zero_kernel<<<CDIV(NNODES, 256), 256>>>();
    csr_count_kernel<<<CDIV(ETOT, 256), 256>>>(ei);
    scan1_kernel<<<NBLK_SCAN, SCAN_B>>>();
    scan2_kernel<<<1, 512>>>();
    scan3_kernel<<<CDIV(NNODES, 256), 256>>>();
    csr_scatter_kernel<<<CDIV(ETOT, 256), 256>>>(ei);

    // ---- MLP stem (no BN fold, no attn) ----
    launch_gemm(x, lin1_w, lin1_b, bufA, NNODES, 2 * HID, F_IN, 1, nullptr, nullptr, nullptr, nullptr);
    launch_gemm(bufA, lin2_w, lin2_b, bufB, NNODES, HID, 2 * HID, 1, nullptr, nullptr, nullptr, nullptr);

    // ---- GAT layer 0 (HID -> W3), attn fused into epilogue ----
    launch_gemm(bufB, w0, nullptr, bufA, NNODES, W3, HID, 0, nullptr, nullptr, as0, ad0);
    bn_zero_kernel<<<2, 256>>>();
    gat_agg_kernel<<<CDIV(NNODES * 32, 256), 256>>>(b0);
    bn_finalize_kernel<<<2, 256>>>(gamma + 0 * W3, beta + 0 * W3);

    // ---- GAT layers 1..3 (prev BN folded into GEMM A-load, attn fused) ----
    for (int i = 0; i < NLAY - 1; i++) {
        const float* W  = wl  + (size_t)i * W3 * W3;
        const float* aS = asl + (size_t)i * NHEAD * HID;
        const float* aD = adl + (size_t)i * NHEAD * HID;
        const float* bb = bl  + (size_t)i * W3;
        launch_gemm(bufB, W, nullptr, bufA, NNODES, W3, W3, 0, sPtr, tPtr, aS, aD);
        bn_zero_kernel<<<2, 256>>>();
        gat_agg_kernel<<<CDIV(NNODES * 32, 256), 256>>>(bb);
        bn_finalize_kernel<<<2, 256>>>(gamma + (size_t)(i + 1) * W3, beta + (size_t)(i + 1) * W3);
    }

    // ---- global mean pool (applies final BN affine) + head ----
    pool_zero_kernel<<<1024, 256>>>();
    pool_kernel<<<CDIV(NNODES * 32, 256), 256>>>(batch);
    head_kernel<<<NGRAPH, 128>>>(lin3_w, lin3_b, lin4_w, lin4_b, out);
}

// round 12
// speedup vs baseline: 3.0610x; 1.0521x over previous
#include <cuda_runtime.h>
#include <cuda_bf16.h>
#include <math.h>
#include <stdint.h>

// ---------------- problem constants ----------------
#define NNODES 100000
#define NEDGES 400000
#define ETOT   (NEDGES + NNODES)   // with self loops = 500000
#define NGRAPH 4000
#define F_IN   32
#define HID    128
#define NHEAD  3
#define W3     (NHEAD * HID)       // 384
#define NCLS   10
#define NLAY   4
#define NEG_SLOPE 0.2f

#define CDIV(a,b) (((a)+(b)-1)/(b))

#define SCAN_B 256
#define NBLK_SCAN CDIV(NNODES, SCAN_B)   // 391

// ---------------- scratch (device globals, no allocation) ----------------
__device__ float         g_bufA[(size_t)NNODES * W3];   // stem intermediate (fp32)
__device__ float         g_bufB[(size_t)NNODES * W3];   // layer in/out (fp32)
__device__ __nv_bfloat16 g_bufH[(size_t)NNODES * W3];   // Hw in bf16 (gather source)
__device__ float g_es[NNODES * NHEAD];
__device__ float g_ed[NNODES * NHEAD];
__device__ int   g_deg[NNODES];
__device__ int   g_off[NNODES + 1];
__device__ int   g_bsum[512];
__device__ int   g_cur[NNODES];
__device__ int   g_csr_src[ETOT];
__device__ float g_colsum[W3];
__device__ float g_colsq[W3];
__device__ float g_s[W3];   // BN folded scale
__device__ float g_t[W3];   // BN folded shift
__device__ float g_pool[(size_t)NGRAPH * W3];
__device__ float g_cnt[NGRAPH];

// ---------------- tf32 tensor-core GEMM, cp.async 3-stage pipeline ---------
// C[M,Nw] = BN(A)[M,K] @ B[K,Nw] (+bias, optional relu).
// If Hb != null: output written as bf16 to Hb instead of fp32 C.
// If attn: emits g_es/g_ed for the block's head (requires Nw==W3, TBN==128).
#define TBM 128
#define TBN 128
#define TBK 32
#define NSTAGE 3
#define A_STRIDE 36   // 32 + 4 pad (floats)
#define B_STRIDE 132  // 128 + 4 pad (floats)
#define A_TILE (TBM * A_STRIDE)
#define B_TILE (TBK * B_STRIDE)
#define GEMM_SMEM_FLOATS (NSTAGE * A_TILE + NSTAGE * B_TILE + 2 * W3 + 2 * TBN + 2 * TBM)
#define GEMM_SMEM_BYTES  (GEMM_SMEM_FLOATS * 4)

__device__ __forceinline__ void cp_async16(uint32_t saddr, const void* gptr, int szbytes) {
    asm volatile("cp.async.cg.shared.global [%0], [%1], 16, %2;\n"
                 :: "r"(saddr), "l"(gptr), "r"(szbytes));
}
__device__ __forceinline__ void cp_commit() {
    asm volatile("cp.async.commit_group;\n");
}
template <int N>
__device__ __forceinline__ void cp_wait() {
    asm volatile("cp.async.wait_group %0;\n" :: "n"(N));
}

__global__ __launch_bounds__(256, 2)
void gemm_tf32_kernel(const float* __restrict__ A, const float* __restrict__ B,
                      const float* __restrict__ bias, float* __restrict__ C,
                      __nv_bfloat16* __restrict__ Hb,
                      int M, int Nw, int K, int relu,
                      const float* __restrict__ bn_s, const float* __restrict__ bn_t,
                      const float* __restrict__ asrc, const float* __restrict__ adst)
{
    extern __shared__ float smem_f[];
    float* As  = smem_f;                       // [NSTAGE][TBM][A_STRIDE]
    float* Bs  = As + NSTAGE * A_TILE;         // [NSTAGE][TBK][B_STRIDE]
    float* Ssh = Bs + NSTAGE * B_TILE;         // [W3]
    float* Tsh = Ssh + W3;                     // [W3]
    float* Asr = Tsh + W3;                     // [TBN]
    float* Adt = Asr + TBN;                    // [TBN]
    float* Esh = Adt + TBN;                    // [TBM]
    float* Dsh = Esh + TBM;                    // [TBM]

    const int bm = blockIdx.y * TBM;
    const int bn = blockIdx.x * TBN;
    const int tid  = threadIdx.x;            // 256
    const int lane = tid & 31;
    const int warp = tid >> 5;
    const int wm = warp & 3;
    const int wn = warp >> 2;
    const bool has_bn = (bn_s != nullptr);
    const bool has_attn = (asrc != nullptr);

    const int a_r  = tid >> 3;
    const int a_c4 = (tid & 7) * 4;
    const int b_k  = tid >> 5;
    const int b_c4 = (tid & 31) * 4;

    if (has_bn)
        for (int k = tid; k < K; k += 256) { Ssh[k] = bn_s[k]; Tsh[k] = bn_t[k]; }
    if (has_attn) {
        const int head = bn / HID;
        if (tid < TBN) {
            Asr[tid] = asrc[head * HID + tid];
            Adt[tid] = adst[head * HID + tid];
        } else if (tid < TBN + TBM) {
            Esh[tid - TBN] = 0.f;
            Dsh[tid - TBN] = 0.f;
        }
    }

    const int nk = K / TBK;

    auto load_stage = [&](int it, int stage) {
        const int k0 = it * TBK;
        float* Asg = As + stage * A_TILE;
        float* Bsg = Bs + stage * B_TILE;
#pragma unroll
        for (int i = 0; i < 4; i++) {
            int r = a_r + i * 32;
            int gr = bm + r;
            uint32_t sa = (uint32_t)__cvta_generic_to_shared(&Asg[r * A_STRIDE + a_c4]);
            cp_async16(sa, A + (size_t)gr * K + k0 + a_c4, (gr < M) ? 16 : 0);
        }
#pragma unroll
        for (int i = 0; i < 4; i++) {
            int kr = b_k + i * 8;
            uint32_t sa = (uint32_t)__cvta_generic_to_shared(&Bsg[kr * B_STRIDE + b_c4]);
            cp_async16(sa, B + (size_t)(k0 + kr) * Nw + bn + b_c4, 16);
        }
        cp_commit();
    };

    float c[2][8][4];
#pragma unroll
    for (int mt = 0; mt < 2; mt++)
#pragma unroll
        for (int nt = 0; nt < 8; nt++)
#pragma unroll
            for (int r = 0; r < 4; r++) c[mt][nt][r] = 0.f;

    const int lq = lane >> 2;
    const int lr = lane & 3;

    load_stage(0, 0);
    if (nk > 1) load_stage(1, 1);

    for (int it = 0; it < nk; it++) {
        if (it + 2 < nk) {
            load_stage(it + 2, (it + 2) % NSTAGE);
            cp_wait<2>();
        } else {
            int rem = nk - 1 - it;
            if (rem >= 2)      cp_wait<2>();
            else if (rem == 1) cp_wait<1>();
            else               cp_wait<0>();
        }
        __syncthreads();

        const int stage = it % NSTAGE;
        const float* Asg = As + stage * A_TILE;
        const float* Bsg = Bs + stage * B_TILE;
        const int k0 = it * TBK;

#pragma unroll
        for (int kk = 0; kk < TBK; kk += 8) {
            float s0v = 1.f, t0v = 0.f, s1v = 1.f, t1v = 0.f;
            if (has_bn) {
                s0v = Ssh[k0 + kk + lr];     t0v = Tsh[k0 + kk + lr];
                s1v = Ssh[k0 + kk + 4 + lr]; t1v = Tsh[k0 + kk + 4 + lr];
            }
            uint32_t a[2][4];
#pragma unroll
            for (int mt = 0; mt < 2; mt++) {
                int row = wm * 32 + mt * 16 + lq;
                float f0 = Asg[row * A_STRIDE + kk + lr];
                float f1 = Asg[(row + 8) * A_STRIDE + kk + lr];
                float f2 = Asg[row * A_STRIDE + kk + 4 + lr];
                float f3 = Asg[(row + 8) * A_STRIDE + kk + 4 + lr];
                if (has_bn) {
                    f0 = fmaf(f0, s0v, t0v); f1 = fmaf(f1, s0v, t0v);
                    f2 = fmaf(f2, s1v, t1v); f3 = fmaf(f3, s1v, t1v);
                }
                a[mt][0] = __float_as_uint(f0);
                a[mt][1] = __float_as_uint(f1);
                a[mt][2] = __float_as_uint(f2);
                a[mt][3] = __float_as_uint(f3);
            }
            uint32_t b[8][2];
#pragma unroll
            for (int nt = 0; nt < 8; nt++) {
                int col = wn * 64 + nt * 8 + lq;
                b[nt][0] = __float_as_uint(Bsg[(kk + lr) * B_STRIDE + col]);
                b[nt][1] = __float_as_uint(Bsg[(kk + 4 + lr) * B_STRIDE + col]);
            }
#pragma unroll
            for (int mt = 0; mt < 2; mt++)
#pragma unroll
                for (int nt = 0; nt < 8; nt++) {
                    asm volatile(
                        "mma.sync.aligned.m16n8k8.row.col.f32.tf32.tf32.f32 "
                        "{%0,%1,%2,%3}, {%4,%5,%6,%7}, {%8,%9}, {%0,%1,%2,%3};"
                        : "+f"(c[mt][nt][0]), "+f"(c[mt][nt][1]),
                          "+f"(c[mt][nt][2]), "+f"(c[mt][nt][3])
                        : "r"(a[mt][0]), "r"(a[mt][1]), "r"(a[mt][2]), "r"(a[mt][3]),
                          "r"(b[nt][0]), "r"(b[nt][1]));
                }
        }
        __syncthreads();
    }

    // epilogue
    float es_p[2][2] = {{0.f, 0.f}, {0.f, 0.f}};
    float ed_p[2][2] = {{0.f, 0.f}, {0.f, 0.f}};

#pragma unroll
    for (int mt = 0; mt < 2; mt++) {
#pragma unroll
        for (int nt = 0; nt < 8; nt++) {
            int row0 = bm + wm * 32 + mt * 16 + lq;
            int lcol = wn * 64 + nt * 8 + lr * 2;
            int col  = bn + lcol;
            float bx = 0.f, by = 0.f;
            if (bias) { bx = bias[col]; by = bias[col + 1]; }
            float v0x = c[mt][nt][0] + bx, v0y = c[mt][nt][1] + by;
            float v1x = c[mt][nt][2] + bx, v1y = c[mt][nt][3] + by;
            if (relu) {
                v0x = fmaxf(v0x, 0.f); v0y = fmaxf(v0y, 0.f);
                v1x = fmaxf(v1x, 0.f); v1y = fmaxf(v1y, 0.f);
            }
            if (Hb) {
                if (row0 < M)
                    *reinterpret_cast<__nv_bfloat162*>(Hb + (size_t)row0 * Nw + col) =
                        __float22bfloat162_rn(make_float2(v0x, v0y));
                if (row0 + 8 < M)
                    *reinterpret_cast<__nv_bfloat162*>(Hb + (size_t)(row0 + 8) * Nw + col) =
                        __float22bfloat162_rn(make_float2(v1x, v1y));
            } else {
                if (row0 < M)
                    *reinterpret_cast<float2*>(C + (size_t)row0 * Nw + col) = make_float2(v0x, v0y);
                if (row0 + 8 < M)
                    *reinterpret_cast<float2*>(C + (size_t)(row0 + 8) * Nw + col) = make_float2(v1x, v1y);
            }
            if (has_attn) {
                float ax = Asr[lcol], ay = Asr[lcol + 1];
                float dx = Adt[lcol], dy = Adt[lcol + 1];
                es_p[mt][0] += v0x * ax + v0y * ay;
                ed_p[mt][0] += v0x * dx + v0y * dy;
                es_p[mt][1] += v1x * ax + v1y * ay;
                ed_p[mt][1] += v1x * dx + v1y * dy;
            }
        }
    }

    if (has_attn) {
#pragma unroll
        for (int mt = 0; mt < 2; mt++)
#pragma unroll
            for (int rh = 0; rh < 2; rh++) {
#pragma unroll
                for (int o = 1; o < 4; o <<= 1) {
                    es_p[mt][rh] += __shfl_xor_sync(0xffffffffu, es_p[mt][rh], o);
                    ed_p[mt][rh] += __shfl_xor_sync(0xffffffffu, ed_p[mt][rh], o);
                }
            }
        if (lr == 0) {
#pragma unroll
            for (int mt = 0; mt < 2; mt++)
#pragma unroll
                for (int rh = 0; rh < 2; rh++) {
                    int rloc = wm * 32 + mt * 16 + rh * 8 + lq;
                    atomicAdd(&Esh[rloc], es_p[mt][rh]);
                    atomicAdd(&Dsh[rloc], ed_p[mt][rh]);
                }
        }
        __syncthreads();
        const int head = bn / HID;
        if (tid < TBM) {
            int row = bm + tid;
            if (row < M) {
                g_es[row * NHEAD + head] = Esh[tid];
                g_ed[row * NHEAD + head] = Dsh[tid];
            }
        }
    }
}

// ---------------- CSR build ------------------------------------------------
__global__ void csr_zero_kernel()
{
    int i = blockIdx.x * blockDim.x + threadIdx.x;
    if (i < NNODES) { g_deg[i] = 0; g_cur[i] = 0; }
}

__global__ void csr_count_kernel(const int* __restrict__ ei)
{
    int i = blockIdx.x * blockDim.x + threadIdx.x;
    if (i >= ETOT) return;
    int d = (i < NEDGES) ? ei[NEDGES + i] : (i - NEDGES);
    atomicAdd(&g_deg[d], 1);
}

__global__ void scan1_kernel()
{
    __shared__ int sh[SCAN_B];
    int t = threadIdx.x;
    int i = blockIdx.x * SCAN_B + t;
    int v = (i < NNODES) ? g_deg[i] : 0;
    sh[t] = v;
    __syncthreads();
#pragma unroll
    for (int o = 1; o < SCAN_B; o <<= 1) {
        int x = (t >= o) ? sh[t - o] : 0;
        __syncthreads();
        sh[t] += x;
        __syncthreads();
    }
    if (i < NNODES) g_off[i] = sh[t] - v;
    if (t == SCAN_B - 1) g_bsum[blockIdx.x] = sh[t];
}

__global__ void scan2_kernel()
{
    __shared__ int sh[512];
    int t = threadIdx.x;
    int v = (t < NBLK_SCAN) ? g_bsum[t] : 0;
    sh[t] = v;
    __syncthreads();
#pragma unroll
    for (int o = 1; o < 512; o <<= 1) {
        int x = (t >= o) ? sh[t - o] : 0;
        __syncthreads();
        sh[t] += x;
        __syncthreads();
    }
    if (t < NBLK_SCAN) g_bsum[t] = sh[t] - v;
}

__global__ void scan3_kernel()
{
    int i = blockIdx.x * blockDim.x + threadIdx.x;
    if (i < NNODES) g_off[i] += g_bsum[i / SCAN_B];
    if (i == 0) g_off[NNODES] = ETOT;
}

__global__ void csr_scatter_kernel(const int* __restrict__ ei)
{
    int i = blockIdx.x * blockDim.x + threadIdx.x;
    if (i >= ETOT) return;
    int s = (i < NEDGES) ? ei[i] : (i - NEDGES);
    int d = (i < NEDGES) ? ei[NEDGES + i] : (i - NEDGES);
    int pos = g_off[d] + atomicAdd(&g_cur[d], 1);
    g_csr_src[pos] = s;
}

// ---------------- zero BN accumulators ------------------------------------
__global__ void bn_zero_kernel()
{
    int i = blockIdx.x * blockDim.x + threadIdx.x;
    if (i < W3) { g_colsum[i] = 0.f; g_colsq[i] = 0.f; }
}

// ---------------- fused softmax + aggregation + BN stats (warp/node) -------
__device__ __forceinline__ float lrelu(float x) {
    return (x > 0.f) ? x : NEG_SLOPE * x;
}

__global__ __launch_bounds__(256)
void gat_agg_kernel(const float* __restrict__ bias)
{
    __shared__ float sh_sum[W3];
    __shared__ float sh_sq[W3];
    const int tid = threadIdx.x;
    for (int i = tid; i < W3; i += 256) { sh_sum[i] = 0.f; sh_sq[i] = 0.f; }
    __syncthreads();

    int gw = (blockIdx.x * 256 + tid) >> 5;
    int lane = tid & 31;
    if (gw < NNODES) {
        const int n = gw;
        const int off0 = g_off[n];
        const int off1 = g_off[n + 1];

        const float ed0 = g_ed[n * 3 + 0];
        const float ed1 = g_ed[n * 3 + 1];
        const float ed2 = g_ed[n * 3 + 2];

        float m0 = -1e30f, m1 = -1e30f, m2 = -1e30f;
        for (int e = off0 + lane; e < off1; e += 32) {
            int s = g_csr_src[e];
            m0 = fmaxf(m0, lrelu(g_es[s * 3 + 0] + ed0));
            m1 = fmaxf(m1, lrelu(g_es[s * 3 + 1] + ed1));
            m2 = fmaxf(m2, lrelu(g_es[s * 3 + 2] + ed2));
        }
#pragma unroll
        for (int o = 16; o > 0; o >>= 1) {
            m0 = fmaxf(m0, __shfl_xor_sync(0xffffffffu, m0, o));
            m1 = fmaxf(m1, __shfl_xor_sync(0xffffffffu, m1, o));
            m2 = fmaxf(m2, __shfl_xor_sync(0xffffffffu, m2, o));
        }
        float s0 = 0.f, s1 = 0.f, s2 = 0.f;
        for (int e = off0 + lane; e < off1; e += 32) {
            int s = g_csr_src[e];
            s0 += __expf(lrelu(g_es[s * 3 + 0] + ed0) - m0);
            s1 += __expf(lrelu(g_es[s * 3 + 1] + ed1) - m1);
            s2 += __expf(lrelu(g_es[s * 3 + 2] + ed2) - m2);
        }
#pragma unroll
        for (int o = 16; o > 0; o >>= 1) {
            s0 += __shfl_xor_sync(0xffffffffu, s0, o);
            s1 += __shfl_xor_sync(0xffffffffu, s1, o);
            s2 += __shfl_xor_sync(0xffffffffu, s2, o);
        }
        const float r0 = 1.f / s0, r1 = 1.f / s1, r2 = 1.f / s2;

        // pass B: gather bf16 Hw; each lane owns feature pairs (j*64 + 2*lane, +1)
        float2 acc[6];
#pragma unroll
        for (int j = 0; j < 6; j++) acc[j] = make_float2(0.f, 0.f);

        for (int e = off0; e < off1; e++) {
            int s = g_csr_src[e];
            float a0 = __expf(lrelu(g_es[s * 3 + 0] + ed0) - m0) * r0;
            float a1 = __expf(lrelu(g_es[s * 3 + 1] + ed1) - m1) * r1;
            float a2 = __expf(lrelu(g_es[s * 3 + 2] + ed2) - m2) * r2;
            const __nv_bfloat162* hp2 =
                reinterpret_cast<const __nv_bfloat162*>(g_bufH + (size_t)s * W3);
#pragma unroll
            for (int j = 0; j < 6; j++) {
                float al = (j < 2) ? a0 : ((j < 4) ? a1 : a2);
                float2 h = __bfloat1622float2(hp2[j * 32 + lane]);
                acc[j].x = fmaf(al, h.x, acc[j].x);
                acc[j].y = fmaf(al, h.y, acc[j].y);
            }
        }
        float* op = g_bufB + (size_t)n * W3;
#pragma unroll
        for (int j = 0; j < 6; j++) {
            int c0 = j * 64 + 2 * lane;
            float vx = acc[j].x + bias[c0];
            float vy = acc[j].y + bias[c0 + 1];
            *reinterpret_cast<float2*>(op + c0) = make_float2(vx, vy);
            atomicAdd(&sh_sum[c0],     vx);
            atomicAdd(&sh_sum[c0 + 1], vy);
            atomicAdd(&sh_sq[c0],      vx * vx);
            atomicAdd(&sh_sq[c0 + 1],  vy * vy);
        }
    }
    __syncthreads();
    for (int i = tid; i < W3; i += 256) {
        atomicAdd(&g_colsum[i], sh_sum[i]);
        atomicAdd(&g_colsq[i], sh_sq[i]);
    }
}

// ---------------- BN finalize: stats + gamma/beta -> s,t --------------------
__global__ void bn_finalize_kernel(const float* __restrict__ gam, const float* __restrict__ bet)
{
    int k = blockIdx.x * blockDim.x + threadIdx.x;
    if (k >= W3) return;
    const float invN = 1.f / (float)NNODES;
    float mu = g_colsum[k] * invN;
    float var = g_colsq[k] * invN - mu * mu;
    float rs = rsqrtf(var + 1e-5f);
    float s = rs * gam[k];
    g_s[k] = s;
    g_t[k] = bet[k] - mu * s;
}

// ---------------- mean pool (applies final BN affine) ----------------------
__global__ void pool_zero_kernel()
{
    int idx = blockIdx.x * blockDim.x + threadIdx.x;
    int total = NGRAPH * W3;
    for (; idx < total; idx += gridDim.x * blockDim.x) g_pool[idx] = 0.f;
    for (int i = blockIdx.x * blockDim.x + threadIdx.x; i < NGRAPH; i += gridDim.x * blockDim.x)
        g_cnt[i] = 0.f;
}

__global__ void pool_kernel(const int* __restrict__ batch)
{
    int gw = (blockIdx.x * blockDim.x + threadIdx.x) >> 5;
    int lane = threadIdx.x & 31;
    if (gw >= NNODES) return;
    int g = batch[gw];
    const float* row = g_bufB + (size_t)gw * W3;
#pragma unroll
    for (int j = 0; j < 12; j++) {
        int c = lane + j * 32;
        float v = fmaf(row[c], g_s[c], g_t[c]);
        atomicAdd(&g_pool[(size_t)g * W3 + c], v);
    }
    if (lane == 0) atomicAdd(&g_cnt[g], 1.f);
}

// ---------------- head: mean, lin3+relu, lin4, log_softmax -----------------
__global__ void head_kernel(const float* __restrict__ w3, const float* __restrict__ b3,
                            const float* __restrict__ w4, const float* __restrict__ b4,
                            float* __restrict__ out)
{
    __shared__ float gv[W3];
    __shared__ float hid[HID];
    __shared__ float lg[NCLS];
    int g = blockIdx.x;
    int t = threadIdx.x;   // 128 threads
    float c = fmaxf(g_cnt[g], 1.f);
    for (int j = t; j < W3; j += 128) gv[j] = g_pool[(size_t)g * W3 + j] / c;
    __syncthreads();
    float acc = b3[t];
    for (int k = 0; k < W3; k++) acc += gv[k] * w3[k * HID + t];
    hid[t] = fmaxf(acc, 0.f);
    __syncthreads();
    if (t < NCLS) {
        float a = b4[t];
        for (int k = 0; k < HID; k++) a += hid[k] * w4[k * NCLS + t];
        lg[t] = a;
    }
    __syncthreads();
    if (t == 0) {
        float mx = lg[0];
        for (int c2 = 1; c2 < NCLS; c2++) mx = fmaxf(mx, lg[c2]);
        float se = 0.f;
        for (int c2 = 0; c2 < NCLS; c2++) se += expf(lg[c2] - mx);
        float l = mx + logf(se);
        for (int c2 = 0; c2 < NCLS; c2++) out[g * NCLS + c2] = lg[c2] - l;
    }
}

// ---------------- host orchestration ---------------------------------------
static inline void launch_gemm(const float* A, const float* B, const float* bias,
                               float* C, __nv_bfloat16* Hb,
                               int M, int Nw, int K, int relu,
                               const float* bn_s, const float* bn_t,
                               const float* asrc, const float* adst)
{
    dim3 grid(Nw / TBN, CDIV(M, TBM));
    gemm_tf32_kernel<<<grid, 256, GEMM_SMEM_BYTES>>>(A, B, bias, C, Hb, M, Nw, K, relu,
                                                     bn_s, bn_t, asrc, adst);
}

extern "C" void kernel_launch(void* const* d_in, const int* in_sizes, int n_in,
                              void* d_out, int out_size)
{
    const float* x       = (const float*)d_in[0];
    const int*   ei      = (const int*)  d_in[1];
    const int*   batch   = (const int*)  d_in[2];
    const float* lin1_w  = (const float*)d_in[3];
    const float* lin1_b  = (const float*)d_in[4];
    const float* lin2_w  = (const float*)d_in[5];
    const float* lin2_b  = (const float*)d_in[6];
    const float* w0      = (const float*)d_in[7];
    const float* as0     = (const float*)d_in[8];
    const float* ad0     = (const float*)d_in[9];
    const float* b0      = (const float*)d_in[10];
    const float* wl      = (const float*)d_in[11];
    const float* asl     = (const float*)d_in[12];
    const float* adl     = (const float*)d_in[13];
    const float* bl      = (const float*)d_in[14];
    const float* gamma   = (const float*)d_in[15];
    const float* beta    = (const float*)d_in[16];
    const float* lin3_w  = (const float*)d_in[17];
    const float* lin3_b  = (const float*)d_in[18];
    const float* lin4_w  = (const float*)d_in[19];
    const float* lin4_b  = (const float*)d_in[20];
    float* out = (float*)d_out;

    static bool attr_set = false;
    if (!attr_set) {
        cudaFuncSetAttribute(gemm_tf32_kernel,
                             cudaFuncAttributeMaxDynamicSharedMemorySize, GEMM_SMEM_BYTES);
        attr_set = true;
    }

    float *bufA, *bufB, *sPtr, *tPtr;
    __nv_bfloat16* bufH;
    cudaGetSymbolAddress((void**)&bufA, g_bufA);
    cudaGetSymbolAddress((void**)&bufB, g_bufB);
    cudaGetSymbolAddress((void**)&bufH, g_bufH);
    cudaGetSymbolAddress((void**)&sPtr, g_s);
    cudaGetSymbolAddress((void**)&tPtr, g_t);

    // ---- CSR build (dst-sorted adjacency), used by all 4 layers ----
    csr_zero_kernel<<<CDIV(NNODES, 256), 256>>>();
    csr_count_kernel<<<CDIV(ETOT, 256), 256>>>(ei);
    scan1_kernel<<<NBLK_SCAN, SCAN_B>>>();
    scan2_kernel<<<1, 512>>>();
    scan3_kernel<<<CDIV(NNODES, 256), 256>>>();
    csr_scatter_kernel<<<CDIV(ETOT, 256), 256>>>(ei);

    // ---- MLP stem (fp32 path) ----
    launch_gemm(x, lin1_w, lin1_b, bufA, nullptr, NNODES, 2 * HID, F_IN, 1,
                nullptr, nullptr, nullptr, nullptr);
    launch_gemm(bufA, lin2_w, lin2_b, bufB, nullptr, NNODES, HID, 2 * HID, 1,
                nullptr, nullptr, nullptr, nullptr);

    // ---- GAT layer 0 (HID -> W3): bf16 Hw out + fused attn ----
    launch_gemm(bufB, w0, nullptr, nullptr, bufH, NNODES, W3, HID, 0,
                nullptr, nullptr, as0, ad0);
    bn_zero_kernel<<<2, 256>>>();
    gat_agg_kernel<<<CDIV(NNODES * 32, 256), 256>>>(b0);
    bn_finalize_kernel<<<2, 256>>>(gamma + 0 * W3, beta + 0 * W3);

    // ---- GAT layers 1..3 (prev BN folded into GEMM A-load) ----
    for (int i = 0; i < NLAY - 1; i++) {
        const float* W  = wl  + (size_t)i * W3 * W3;
        const float* aS = asl + (size_t)i * NHEAD * HID;
        const float* aD = adl + (size_t)i * NHEAD * HID;
        const float* bb = bl  + (size_t)i * W3;
        launch_gemm(bufB, W, nullptr, nullptr, bufH, NNODES, W3, W3, 0,
                    sPtr, tPtr, aS, aD);
        bn_zero_kernel<<<2, 256>>>();
        gat_agg_kernel<<<CDIV(NNODES * 32, 256), 256>>>(bb);
        bn_finalize_kernel<<<2, 256>>>(gamma + (size_t)(i + 1) * W3, beta + (size_t)(i + 1) * W3);
    }

    // ---- global mean pool (applies final BN affine) + head ----
    pool_zero_kernel<<<1024, 256>>>();
    pool_kernel<<<CDIV(NNODES * 32, 256), 256>>>(batch);
    head_kernel<<<NGRAPH, 128>>>(lin3_w, lin3_b, lin4_w, lin4_b, out);
}